// round 13
// baseline (speedup 1.0000x reference)
#include <cuda_runtime.h>
#include <cuda_bf16.h>
#include <math.h>
#include <stdint.h>

#define Lc 26
#define Tc 512
#define Dc 768
#define NHc 12
#define NGc 4
#define GSc 3
#define HDc 64
#define FFc 2048
#define CACHEc 1536
#define Sc 2048
#define Vocab 32000
#define WINc 512
#define QKVW 1280
typedef __nv_bfloat16 bf16;

#define SZ_WQKV 25559040
#define SZ_WOUT 15335424
#define SZ_WFF  40894464
#define SZ_WLM  24576000
#define KVL (NGc * Sc * HDc)
#define NTD (NHc * Tc * HDc)
#define FZ 3
#define TF (Tc * FFc)

// ---------------- scratch ----------------
__device__ float g_h[Tc * Dc];
__device__ float g_qkv[3 * Tc * QKVW];
__device__ float g_t1[4 * Tc * Dc];
__device__ float g_aop[FZ * NTD];
__device__ float g_rsp[FZ * NHc * Tc];
__device__ float g_gp[3 * TF];
__device__ float g_up2[3 * TF];
__device__ bf16 bx_h[Tc * Dc], bx_l[Tc * Dc];
__device__ bf16 bat_h[Tc * Dc], bat_l[Tc * Dc];
__device__ bf16 bgt_h[TF], bgt_l[TF];
__device__ bf16 bq_h[NTD], bq_l[NTD];
__device__ bf16 bk_h[Lc * KVL], bk_l[Lc * KVL];
__device__ bf16 bv_h[Lc * KVL], bv_l[Lc * KVL];
__device__ bf16 wqkv_h[SZ_WQKV], wqkv_l[SZ_WQKV];
__device__ bf16 wout_h[SZ_WOUT], wout_l[SZ_WOUT];
__device__ bf16 wgt_h[SZ_WFF], wgt_l[SZ_WFF];
__device__ bf16 wup_h[SZ_WFF], wup_l[SZ_WFF];
__device__ bf16 wdn_h[SZ_WFF], wdn_l[SZ_WFF];
__device__ bf16 wlm_h[SZ_WLM], wlm_l[SZ_WLM];

// ---------------- asm helpers ----------------
__device__ __forceinline__ uint32_t cvta(const void* p) {
    return (uint32_t)__cvta_generic_to_shared(p);
}
#define LDSM4(r, a) asm volatile( \
    "ldmatrix.sync.aligned.m8n8.x4.shared.b16 {%0,%1,%2,%3},[%4];\n" \
    : "=r"((r)[0]), "=r"((r)[1]), "=r"((r)[2]), "=r"((r)[3]) : "r"(a))
#define LDSM4T(r, a) asm volatile( \
    "ldmatrix.sync.aligned.m8n8.x4.trans.shared.b16 {%0,%1,%2,%3},[%4];\n" \
    : "=r"((r)[0]), "=r"((r)[1]), "=r"((r)[2]), "=r"((r)[3]) : "r"(a))
#define MMA16(c, a, b0, b1) asm volatile( \
    "mma.sync.aligned.m16n8k16.row.col.f32.bf16.bf16.f32 " \
    "{%0,%1,%2,%3},{%4,%5,%6,%7},{%8,%9},{%0,%1,%2,%3};\n" \
    : "+f"((c)[0]), "+f"((c)[1]), "+f"((c)[2]), "+f"((c)[3]) \
    : "r"((a)[0]), "r"((a)[1]), "r"((a)[2]), "r"((a)[3]), "r"(b0), "r"(b1))
#define CPA16(d, s) asm volatile("cp.async.cg.shared.global [%0],[%1],16;\n" :: "r"(d), "l"(s))
#define CPCOMMIT() asm volatile("cp.async.commit_group;\n")
#define CPWAIT(n) asm volatile("cp.async.wait_group %0;\n" :: "n"(n))

__device__ __forceinline__ void splitstore(bf16* ph, bf16* pl, size_t i, float v) {
    bf16 h = __float2bfloat16(v);
    ph[i] = h;
    pl[i] = __float2bfloat16(v - __bfloat162float(h));
}

__device__ __forceinline__ void split4v(float4 v, uint2& hi, uint2& lo) {
    __nv_bfloat162 h0, h1, l0, l1;
    h0.x = __float2bfloat16(v.x); h0.y = __float2bfloat16(v.y);
    h1.x = __float2bfloat16(v.z); h1.y = __float2bfloat16(v.w);
    l0.x = __float2bfloat16(v.x - __bfloat162float(h0.x));
    l0.y = __float2bfloat16(v.y - __bfloat162float(h0.y));
    l1.x = __float2bfloat16(v.z - __bfloat162float(h1.x));
    l1.y = __float2bfloat16(v.w - __bfloat162float(h1.y));
    hi.x = *(uint32_t*)&h0; hi.y = *(uint32_t*)&h1;
    lo.x = *(uint32_t*)&l0; lo.y = *(uint32_t*)&l1;
}

__device__ __forceinline__ float softcap_exp(float s) {
    float u = __expf(s * 0.005f);
    return __expf(50.f - 100.f / (u + 1.f));
}
__device__ __forceinline__ float fast_tanh(float y) {
    return 1.f - 2.f / (__expf(2.f * y) + 1.f);
}
__device__ __forceinline__ float warpSum(float v) {
#pragma unroll
    for (int o = 16; o; o >>= 1) v += __shfl_xor_sync(0xffffffffu, v, o);
    return v;
}

// ---------------- elementwise ----------------
__global__ void k_split4(const float* __restrict__ s, bf16* __restrict__ hi,
                         bf16* __restrict__ lo, int n4) {
    int i = blockIdx.x * blockDim.x + threadIdx.x;
    if (i >= n4) return;
    float4 v = ((const float4*)s)[i];
    uint2 h, l;
    split4v(v, h, l);
    ((uint2*)hi)[i] = h;
    ((uint2*)lo)[i] = l;
}

__global__ void k_convall(const float* __restrict__ ks, const float* __restrict__ vs,
                          bf16* __restrict__ kh, bf16* __restrict__ kl,
                          bf16* __restrict__ vh, bf16* __restrict__ vl) {
    int idx = blockIdx.x * blockDim.x + threadIdx.x;
    if (idx >= Lc * 196608) return;
    int layer = idx / 196608;
    int r = idx - layer * 196608;
    const float* ksl = ks + (size_t)layer * 393216;
    const float* vsl = vs + (size_t)layer * 393216;
    size_t kvoff = (size_t)layer * KVL;
    if (r < 98304) {
        int i4 = r * 4;
        int g = i4 / (CACHEc * HDc), rr = i4 - g * (CACHEc * HDc);
        size_t dst = kvoff + (size_t)g * Sc * HDc + rr;
        float4 v = ((const float4*)ksl)[r];
        uint2 h, l;
        split4v(v, h, l);
        *(uint2*)(kh + dst) = h;
        *(uint2*)(kl + dst) = l;
    } else {
        int j4 = (r - 98304) * 4;
        int row = j4 / CACHEc, c = j4 - row * CACHEc;
        size_t dst = kvoff + (size_t)row * Sc + c;
        float4 v = ((const float4*)vsl)[r - 98304];
        uint2 h, l;
        split4v(v, h, l);
        *(uint2*)(vh + dst) = h;
        *(uint2*)(vl + dst) = l;
    }
}

// warp-per-row init: h = e; out = split(rmsnorm(e, w))
__global__ void k_init(const float* __restrict__ e, const float* __restrict__ w,
                       float* __restrict__ h, bf16* __restrict__ oh, bf16* __restrict__ ol) {
    int wid = threadIdx.x >> 5, lane = threadIdx.x & 31;
    int row = blockIdx.x * 8 + wid;
    const float* x = e + (size_t)row * Dc;
    float v[24];
    float ss = 0.f;
#pragma unroll
    for (int i = 0; i < 24; i++) {
        v[i] = x[lane + i * 32];
        ss += v[i] * v[i];
    }
    float rs = rsqrtf(warpSum(ss) / Dc + 1e-6f);
#pragma unroll
    for (int i = 0; i < 24; i++) {
        int d = lane + i * 32;
        h[(size_t)row * Dc + d] = v[i];
        splitstore(oh, ol, (size_t)row * Dc + d, v[i] * rs * (1.f + w[d]));
    }
}

// warp-per-row: h += rmsnorm(sum_z t1[z], wpost); out = split(rmsnorm(h, wpre))
__global__ void k_fuse(float* __restrict__ h, const float* __restrict__ t1, int Z,
                       const float* __restrict__ wpost, const float* __restrict__ wpre,
                       bf16* __restrict__ oh, bf16* __restrict__ ol) {
    int wid = threadIdx.x >> 5, lane = threadIdx.x & 31;
    int row = blockIdx.x * 8 + wid;
    float x[24];
    float ss = 0.f;
#pragma unroll
    for (int i = 0; i < 24; i++) {
        int d = lane + i * 32;
        float v = 0.f;
        for (int z = 0; z < Z; z++) v += t1[(size_t)z * Tc * Dc + (size_t)row * Dc + d];
        x[i] = v;
        ss += v * v;
    }
    float rs = rsqrtf(warpSum(ss) / Dc + 1e-6f);
    float hv[24];
    float ss2 = 0.f;
#pragma unroll
    for (int i = 0; i < 24; i++) {
        int d = lane + i * 32;
        float t = h[(size_t)row * Dc + d] + x[i] * rs * (1.f + wpost[d]);
        hv[i] = t;
        h[(size_t)row * Dc + d] = t;
        ss2 += t * t;
    }
    float rs2 = rsqrtf(warpSum(ss2) / Dc + 1e-6f);
#pragma unroll
    for (int i = 0; i < 24; i++) {
        int d = lane + i * 32;
        splitstore(oh, ol, (size_t)row * Dc + d, hv[i] * rs2 * (1.f + wpre[d]));
    }
}

// warp-per-(t,g): qkv split-K sum (3) + head rmsnorm + rope + cache append
__global__ void k_qkprep(const float* __restrict__ qkv,
                         const float* __restrict__ qw, const float* __restrict__ kw,
                         const float* __restrict__ cos_, const float* __restrict__ sin_,
                         bf16* __restrict__ kh, bf16* __restrict__ kl,
                         bf16* __restrict__ vh, bf16* __restrict__ vl) {
    int wid = threadIdx.x >> 5, lane = threadIdx.x & 31;
    int p = blockIdx.x * 8 + wid;          // p = t*NGc + g
    int t = p >> 2, g = p & 3;
    size_t boff = (size_t)p * (GSc + 2) * HDc;
    const float* b0 = qkv + boff;
    const float* b1 = b0 + (size_t)Tc * QKVW;
    const float* b2 = b1 + (size_t)Tc * QKVW;
    float c0 = cos_[t * HDc + lane], c1 = cos_[t * HDc + lane + 32];
    float s0 = sin_[t * HDc + lane], s1 = sin_[t * HDc + lane + 32];
#pragma unroll
    for (int j = 0; j <= GSc; j++) {
        int o0i = j * HDc + lane, o1i = j * HDc + lane + 32;
        float v0 = b0[o0i] + b1[o0i] + b2[o0i];
        float v1 = b0[o1i] + b1[o1i] + b2[o1i];
        float rs = rsqrtf(warpSum(v0 * v0 + v1 * v1) * (1.f / HDc) + 1e-6f);
        const float* wgt = (j < GSc) ? qw : kw;
        float nv0 = v0 * rs * (1.f + wgt[lane]);
        float nv1 = v1 * rs * (1.f + wgt[lane + 32]);
        float out0 = nv0 * c0 - nv1 * s0;
        float out1 = nv1 * c1 + nv0 * s1;
        if (j < GSc) {
            size_t base = ((size_t)(g * GSc + j) * Tc + t) * HDc;
            splitstore(bq_h, bq_l, base + lane, out0);
            splitstore(bq_h, bq_l, base + lane + 32, out1);
        } else {
            size_t base = ((size_t)g * Sc + CACHEc + t) * HDc;
            splitstore(kh, kl, base + lane, out0);
            splitstore(kh, kl, base + lane + 32, out1);
        }
    }
    int vi0 = (GSc + 1) * HDc + lane, vi1 = vi0 + 32;
    float vv0 = b0[vi0] + b1[vi0] + b2[vi0];
    float vv1 = b0[vi1] + b1[vi1] + b2[vi1];
    splitstore(vh, vl, (size_t)(g * HDc + lane) * Sc + CACHEc + t, vv0);
    splitstore(vh, vl, (size_t)(g * HDc + lane + 32) * Sc + CACHEc + t, vv1);
}

__global__ void k_fcomb(const float* __restrict__ aop, const float* __restrict__ rsp,
                        bf16* __restrict__ oh, bf16* __restrict__ ol) {
    int i = blockIdx.x * blockDim.x + threadIdx.x;
    if (i >= NTD) return;
    int h = i / (Tc * HDc);
    int rem = i - h * (Tc * HDc);
    int t = rem / HDc, d = rem - (rem / HDc) * HDc;
    float r = 0.f, o = 0.f;
#pragma unroll
    for (int z = 0; z < FZ; z++) {
        r += rsp[((size_t)z * NHc + h) * Tc + t];
        o += aop[(size_t)z * NTD + i];
    }
    splitstore(oh, ol, (size_t)t * Dc + h * HDc + d, o / r);
}

// ff combine over 3 partials: gelu(g)*(u) -> bf16 split
__global__ void k_gcomb(const float* __restrict__ gp, const float* __restrict__ up,
                        bf16* __restrict__ oh, bf16* __restrict__ ol) {
    int i = blockIdx.x * blockDim.x + threadIdx.x;
    if (i >= TF) return;
    float x = gp[i] + gp[TF + i] + gp[2 * TF + i];
    float u = up[i] + up[TF + i] + up[2 * TF + i];
    float y = 0.7978845608028654f * (x + 0.044715f * x * x * x);
    splitstore(oh, ol, i, 0.5f * x * (1.f + fast_tanh(y)) * u);
}

// ============ templated GEMM: BM x 64 tile, BK=32, split-K via blockIdx.z ============
template <int BM, int WMW>
__global__ void __launch_bounds__(256) k_mm_t(const bf16* __restrict__ Ah,
                                              const bf16* __restrict__ Al,
                                              const bf16* __restrict__ Bh,
                                              const bf16* __restrict__ Bl,
                                              float* __restrict__ C, int N, int K,
                                              size_t cstride) {
    constexpr int WNW = 8 / WMW;
    constexpr int WROWS = BM / WMW;
    constexpr int WCOLS = 64 / WNW;
    constexpr int N8 = WCOLS / 8;
    constexpr int NB = WCOLS / 16;
    constexpr int AJ = BM / 64;
    extern __shared__ char dsm[];
    bf16* sA = (bf16*)dsm;
    bf16* sB = (bf16*)(dsm + 2 * 2 * BM * 40 * 2);
#define SAi(st, p, r, c) (sA + ((((st)*2 + (p)) * BM + (r)) * 40 + (c)))
#define SBi(st, p, r, c) (sB + ((((st)*2 + (p)) * 32 + (r)) * 72 + (c)))
    int z = blockIdx.z;
    int Ksub = K / gridDim.z;
    Ah += (size_t)z * Ksub;
    Al += (size_t)z * Ksub;
    Bh += (size_t)z * Ksub * N;
    Bl += (size_t)z * Ksub * N;
    C += (size_t)z * cstride;
    int tid = threadIdx.x, lane = tid & 31, warp = tid >> 5;
    int wm = warp % WMW, wn = warp / WMW;
    int bm = blockIdx.y * BM, bn = blockIdx.x * 64;
    int nIt = Ksub >> 5;
    int br = tid >> 3, bc = (tid & 7) << 3;
    const bf16* pBh = Bh + (size_t)br * N + bn + bc;
    const bf16* pBl = Bl + (size_t)br * N + bn + bc;
    float acc[2][N8][4] = {};
#pragma unroll
    for (int j = 0; j < AJ; j++) {
        int id = tid + j * 256, r = id >> 2, c = (id & 3) << 3;
        CPA16(cvta(SAi(0, 0, r, c)), Ah + (size_t)(bm + r) * K + c);
        CPA16(cvta(SAi(0, 1, r, c)), Al + (size_t)(bm + r) * K + c);
    }
    CPA16(cvta(SBi(0, 0, br, bc)), pBh);
    CPA16(cvta(SBi(0, 1, br, bc)), pBl);
    CPCOMMIT();
    for (int it = 0; it < nIt; it++) {
        int st = it & 1;
        if (it + 1 < nIt) {
            int k0 = (it + 1) << 5;
#pragma unroll
            for (int j = 0; j < AJ; j++) {
                int id = tid + j * 256, r = id >> 2, c = (id & 3) << 3;
                CPA16(cvta(SAi(st ^ 1, 0, r, c)), Ah + (size_t)(bm + r) * K + k0 + c);
                CPA16(cvta(SAi(st ^ 1, 1, r, c)), Al + (size_t)(bm + r) * K + k0 + c);
            }
            CPA16(cvta(SBi(st ^ 1, 0, br, bc)), pBh + (size_t)k0 * N);
            CPA16(cvta(SBi(st ^ 1, 1, br, bc)), pBl + (size_t)k0 * N);
            CPCOMMIT(); CPWAIT(1);
        } else CPWAIT(0);
        __syncthreads();
#pragma unroll
        for (int kp = 0; kp < 2; kp++) {
            uint32_t ah2[2][4], al2[2][4], bh2[4 * NB], bl2[4 * NB];
#pragma unroll
            for (int mt = 0; mt < 2; mt++) {
                int r = wm * WROWS + mt * 16 + (lane & 15), c = kp * 16 + ((lane >> 4) << 3);
                LDSM4(ah2[mt], cvta(SAi(st, 0, r, c)));
                LDSM4(al2[mt], cvta(SAi(st, 1, r, c)));
            }
            int bg = lane >> 3;
            int kr = kp * 16 + ((bg & 1) << 3) + (lane & 7);
#pragma unroll
            for (int nb = 0; nb < NB; nb++) {
                int nc = wn * WCOLS + nb * 16 + ((bg >> 1) << 3);
                LDSM4T(&bh2[nb * 4], cvta(SBi(st, 0, kr, nc)));
                LDSM4T(&bl2[nb * 4], cvta(SBi(st, 1, kr, nc)));
            }
#pragma unroll
            for (int mt = 0; mt < 2; mt++)
#pragma unroll
                for (int nt = 0; nt < N8; nt++) {
                    int f = (nt >> 1) * 4 + ((nt & 1) << 1);
                    MMA16(acc[mt][nt], ah2[mt], bh2[f], bh2[f + 1]);
                    MMA16(acc[mt][nt], ah2[mt], bl2[f], bl2[f + 1]);
                    MMA16(acc[mt][nt], al2[mt], bh2[f], bh2[f + 1]);
                }
        }
        __syncthreads();
    }
#pragma unroll
    for (int mt = 0; mt < 2; mt++)
#pragma unroll
        for (int nt = 0; nt < N8; nt++) {
            int r0 = bm + wm * WROWS + mt * 16 + (lane >> 2);
            int c0 = bn + wn * WCOLS + nt * 8 + 2 * (lane & 3);
            *(float2*)(C + (size_t)r0 * N + c0) = make_float2(acc[mt][nt][0], acc[mt][nt][1]);
            *(float2*)(C + (size_t)(r0 + 8) * N + c0) = make_float2(acc[mt][nt][2], acc[mt][nt][3]);
        }
#undef SAi
#undef SBi
}

// ============ dual GEMM (gate|up), split-K, fp32 partials ============
__global__ void __launch_bounds__(256) k_mmff(const bf16* __restrict__ Ah,
                                              const bf16* __restrict__ Al,
                                              const bf16* __restrict__ B0h,
                                              const bf16* __restrict__ B0l,
                                              const bf16* __restrict__ B1h,
                                              const bf16* __restrict__ B1l,
                                              float* __restrict__ Cg,
                                              float* __restrict__ Cu) {
    extern __shared__ char dsm[];
    bf16* sA = (bf16*)dsm;
    bf16* sB0 = (bf16*)(dsm + 2 * 2 * 64 * 40 * 2);
    bf16* sB1 = (bf16*)(dsm + 2 * 2 * 64 * 40 * 2 + 2 * 2 * 32 * 72 * 2);
#define SAi(st, p, r, c) (sA + ((((st)*2 + (p)) * 64 + (r)) * 40 + (c)))
#define SB0i(st, p, r, c) (sB0 + ((((st)*2 + (p)) * 32 + (r)) * 72 + (c)))
#define SB1i(st, p, r, c) (sB1 + ((((st)*2 + (p)) * 32 + (r)) * 72 + (c)))
    const int N = FFc, K = Dc;
    int z = blockIdx.z;
    int Ksub = K / gridDim.z;
    const bf16* Ahz = Ah + (size_t)z * Ksub;
    const bf16* Alz = Al + (size_t)z * Ksub;
    const bf16* B0hz = B0h + (size_t)z * Ksub * N;
    const bf16* B0lz = B0l + (size_t)z * Ksub * N;
    const bf16* B1hz = B1h + (size_t)z * Ksub * N;
    const bf16* B1lz = B1l + (size_t)z * Ksub * N;
    Cg += (size_t)z * TF;
    Cu += (size_t)z * TF;
    int tid = threadIdx.x, lane = tid & 31, warp = tid >> 5;
    int wm = warp & 1, wn = warp >> 1;
    int bm = blockIdx.y * 64, bn = blockIdx.x * 64;
    int br = tid >> 3, bc = (tid & 7) << 3;
    size_t boff = (size_t)br * N + bn + bc;
    float ag[2][2][4] = {}, au[2][2][4] = {};
    {
        int r = tid >> 2, c = (tid & 3) << 3;
        CPA16(cvta(SAi(0, 0, r, c)), Ahz + (size_t)(bm + r) * K + c);
        CPA16(cvta(SAi(0, 1, r, c)), Alz + (size_t)(bm + r) * K + c);
    }
    CPA16(cvta(SB0i(0, 0, br, bc)), B0hz + boff); CPA16(cvta(SB0i(0, 1, br, bc)), B0lz + boff);
    CPA16(cvta(SB1i(0, 0, br, bc)), B1hz + boff); CPA16(cvta(SB1i(0, 1, br, bc)), B1lz + boff);
    CPCOMMIT();
    int nIt = Ksub >> 5;
    for (int it = 0; it < nIt; it++) {
        int st = it & 1;
        if (it + 1 < nIt) {
            int k0 = (it + 1) << 5;
            int r = tid >> 2, c = (tid & 3) << 3;
            CPA16(cvta(SAi(st ^ 1, 0, r, c)), Ahz + (size_t)(bm + r) * K + k0 + c);
            CPA16(cvta(SAi(st ^ 1, 1, r, c)), Alz + (size_t)(bm + r) * K + k0 + c);
            CPA16(cvta(SB0i(st ^ 1, 0, br, bc)), B0hz + boff + (size_t)k0 * N);
            CPA16(cvta(SB0i(st ^ 1, 1, br, bc)), B0lz + boff + (size_t)k0 * N);
            CPA16(cvta(SB1i(st ^ 1, 0, br, bc)), B1hz + boff + (size_t)k0 * N);
            CPA16(cvta(SB1i(st ^ 1, 1, br, bc)), B1lz + boff + (size_t)k0 * N);
            CPCOMMIT(); CPWAIT(1);
        } else CPWAIT(0);
        __syncthreads();
#pragma unroll
        for (int kp = 0; kp < 2; kp++) {
            uint32_t ah2[2][4], al2[2][4], b0h[4], b0l[4], b1h[4], b1l[4];
#pragma unroll
            for (int mt = 0; mt < 2; mt++) {
                int r = wm * 32 + mt * 16 + (lane & 15), c = kp * 16 + ((lane >> 4) << 3);
                LDSM4(ah2[mt], cvta(SAi(st, 0, r, c)));
                LDSM4(al2[mt], cvta(SAi(st, 1, r, c)));
            }
            int bg = lane >> 3;
            int kr = kp * 16 + ((bg & 1) << 3) + (lane & 7);
            int nc = wn * 16 + ((bg >> 1) << 3);
            LDSM4T(b0h, cvta(SB0i(st, 0, kr, nc)));
            LDSM4T(b0l, cvta(SB0i(st, 1, kr, nc)));
            LDSM4T(b1h, cvta(SB1i(st, 0, kr, nc)));
            LDSM4T(b1l, cvta(SB1i(st, 1, kr, nc)));
#pragma unroll
            for (int mt = 0; mt < 2; mt++)
#pragma unroll
                for (int nt = 0; nt < 2; nt++) {
                    MMA16(ag[mt][nt], ah2[mt], b0h[2 * nt], b0h[2 * nt + 1]);
                    MMA16(ag[mt][nt], ah2[mt], b0l[2 * nt], b0l[2 * nt + 1]);
                    MMA16(ag[mt][nt], al2[mt], b0h[2 * nt], b0h[2 * nt + 1]);
                    MMA16(au[mt][nt], ah2[mt], b1h[2 * nt], b1h[2 * nt + 1]);
                    MMA16(au[mt][nt], ah2[mt], b1l[2 * nt], b1l[2 * nt + 1]);
                    MMA16(au[mt][nt], al2[mt], b1h[2 * nt], b1h[2 * nt + 1]);
                }
        }
        __syncthreads();
    }
#pragma unroll
    for (int mt = 0; mt < 2; mt++)
#pragma unroll
        for (int nt = 0; nt < 2; nt++) {
            int r0 = bm + wm * 32 + mt * 16 + (lane >> 2);
            int c0 = bn + wn * 16 + nt * 8 + 2 * (lane & 3);
            *(float2*)(Cg + (size_t)r0 * N + c0) = make_float2(ag[mt][nt][0], ag[mt][nt][1]);
            *(float2*)(Cg + (size_t)(r0 + 8) * N + c0) = make_float2(ag[mt][nt][2], ag[mt][nt][3]);
            *(float2*)(Cu + (size_t)r0 * N + c0) = make_float2(au[mt][nt][0], au[mt][nt][1]);
            *(float2*)(Cu + (size_t)(r0 + 8) * N + c0) = make_float2(au[mt][nt][2], au[mt][nt][3]);
        }
#undef SAi
#undef SB0i
#undef SB1i
}

// ============ flash attention: split-S partials, 2-stage KV pipeline ============
__global__ void __launch_bounds__(256) k_flash(const bf16* __restrict__ kh,
                                               const bf16* __restrict__ kl,
                                               const bf16* __restrict__ vhp,
                                               const bf16* __restrict__ vlp,
                                               float* __restrict__ aop,
                                               float* __restrict__ rsp,
                                               int is_local) {
    extern __shared__ char dsm[];
    bf16* sm = (bf16*)dsm;
    bf16* sQh = sm;
    bf16* sQl = sm + 4608;
    bf16* sKV[2][4];
    sKV[0][0] = sm + 2 * 4608; sKV[0][1] = sm + 3 * 4608;
    sKV[0][2] = sm + 4 * 4608; sKV[0][3] = sm + 5 * 4608;
    sKV[1][0] = sm + 6 * 4608; sKV[1][1] = sm + 7 * 4608;
    sKV[1][2] = sm + 8 * 4608; sKV[1][3] = sm + 9 * 4608;
    bf16* sPh = sm + 10 * 4608;
    bf16* sPl = sm + 11 * 4608;
    float* srs = (float*)(sm + 12 * 4608);
    int h = blockIdx.y, g = h / GSc, t0 = blockIdx.x * 64;
    int z = blockIdx.z;
    int tid = threadIdx.x, lane = tid & 31, warp = tid >> 5;
    int wm = warp & 1, wn = warp >> 1;
    const bf16* Qh_ = bq_h + ((size_t)h * Tc + t0) * HDc;
    const bf16* Ql_ = bq_l + ((size_t)h * Tc + t0) * HDc;
#pragma unroll
    for (int i = 0; i < 2; i++) {
        int c = tid + i * 256, r = c >> 3, cc = (c & 7) << 3;
        CPA16(cvta(sQh + r * 72 + cc), Qh_ + r * HDc + cc);
        CPA16(cvta(sQl + r * 72 + cc), Ql_ + r * HDc + cc);
    }
    if (tid < 64) srs[tid] = 0.f;
    float ao[2][2][4] = {};
    float rs_[2][2] = {};
    int s_lo = is_local ? ((CACHEc + t0 - WINc + 1) >> 6) : 0;
    int s_hi = (CACHEc + t0 + 63) >> 6;
    int nt_all = s_hi - s_lo + 1;
    int chunk = (nt_all + (int)gridDim.z - 1) / (int)gridDim.z;
    int my_lo = s_lo + z * chunk;
    int my_hi = my_lo + chunk - 1;
    if (my_hi > s_hi) my_hi = s_hi;

    auto loadkv = [&](int s0, int st) {
        const bf16* Kh_ = kh + ((size_t)g * Sc + s0) * HDc;
        const bf16* Kl_ = kl + ((size_t)g * Sc + s0) * HDc;
        const bf16* Vh_ = vhp + (size_t)g * HDc * Sc + s0;
        const bf16* Vl_ = vlp + (size_t)g * HDc * Sc + s0;
#pragma unroll
        for (int i = 0; i < 2; i++) {
            int c = tid + i * 256, r = c >> 3, cc = (c & 7) << 3;
            CPA16(cvta(sKV[st][0] + r * 72 + cc), Kh_ + r * HDc + cc);
            CPA16(cvta(sKV[st][1] + r * 72 + cc), Kl_ + r * HDc + cc);
            CPA16(cvta(sKV[st][2] + r * 72 + cc), Vh_ + (size_t)r * Sc + cc);
            CPA16(cvta(sKV[st][3] + r * 72 + cc), Vl_ + (size_t)r * Sc + cc);
        }
    };

    if (my_lo <= my_hi) loadkv(my_lo << 6, 0);
    CPCOMMIT();
    __syncthreads();

    for (int stile = my_lo; stile <= my_hi; stile++) {
        int st = (stile - my_lo) & 1;
        int s0 = stile << 6;
        if (stile < my_hi) {
            loadkv((stile + 1) << 6, st ^ 1);
            CPCOMMIT();
            CPWAIT(1);
        } else {
            CPWAIT(0);
        }
        __syncthreads();
        bf16 *cKh = sKV[st][0], *cKl = sKV[st][1], *cVh = sKV[st][2], *cVl = sKV[st][3];
        float sc_[2][2][4] = {};
#pragma unroll
        for (int kp = 0; kp < 4; kp++) {
            uint32_t ah2[2][4], al2[2][4], bh2[4], bl2[4];
#pragma unroll
            for (int mt = 0; mt < 2; mt++) {
                int r = wm * 32 + mt * 16 + (lane & 15), c = kp * 16 + ((lane >> 4) << 3);
                LDSM4(ah2[mt], cvta(sQh + r * 72 + c));
                LDSM4(al2[mt], cvta(sQl + r * 72 + c));
            }
            int bg = lane >> 3;
            int nr = wn * 16 + ((bg >> 1) << 3) + (lane & 7);
            int kc = kp * 16 + ((bg & 1) << 3);
            LDSM4(bh2, cvta(cKh + nr * 72 + kc));
            LDSM4(bl2, cvta(cKl + nr * 72 + kc));
#pragma unroll
            for (int mt = 0; mt < 2; mt++)
#pragma unroll
                for (int nt = 0; nt < 2; nt++) {
                    MMA16(sc_[mt][nt], ah2[mt], bh2[2 * nt], bh2[2 * nt + 1]);
                    MMA16(sc_[mt][nt], ah2[mt], bl2[2 * nt], bl2[2 * nt + 1]);
                    MMA16(sc_[mt][nt], al2[mt], bh2[2 * nt], bh2[2 * nt + 1]);
                }
        }
#pragma unroll
        for (int mt = 0; mt < 2; mt++)
#pragma unroll
            for (int nt = 0; nt < 2; nt++)
#pragma unroll
                for (int e = 0; e < 4; e++) {
                    int tl = wm * 32 + mt * 16 + (lane >> 2) + (e >= 2 ? 8 : 0);
                    int sl = wn * 16 + nt * 8 + 2 * (lane & 3) + (e & 1);
                    int sp = s0 + sl, qpos = CACHEc + t0 + tl;
                    bool ok = (sp <= qpos) && (!is_local || sp > qpos - WINc);
                    float p = ok ? softcap_exp(sc_[mt][nt][e]) : 0.f;
                    rs_[mt][e >= 2 ? 1 : 0] += p;
                    bf16 ph = __float2bfloat16(p);
                    sPh[tl * 72 + sl] = ph;
                    sPl[tl * 72 + sl] = __float2bfloat16(p - __bfloat162float(ph));
                }
        __syncthreads();
#pragma unroll
        for (int kp = 0; kp < 4; kp++) {
            uint32_t ah2[2][4], al2[2][4], bh2[4], bl2[4];
#pragma unroll
            for (int mt = 0; mt < 2; mt++) {
                int r = wm * 32 + mt * 16 + (lane & 15), c = kp * 16 + ((lane >> 4) << 3);
                LDSM4(ah2[mt], cvta(sPh + r * 72 + c));
                LDSM4(al2[mt], cvta(sPl + r * 72 + c));
            }
            int bg = lane >> 3;
            int nr = wn * 16 + ((bg >> 1) << 3) + (lane & 7);
            int kc = kp * 16 + ((bg & 1) << 3);
            LDSM4(bh2, cvta(cVh + nr * 72 + kc));
            LDSM4(bl2, cvta(cVl + nr * 72 + kc));
#pragma unroll
            for (int mt = 0; mt < 2; mt++)
#pragma unroll
                for (int nt = 0; nt < 2; nt++) {
                    MMA16(ao[mt][nt], ah2[mt], bh2[2 * nt], bh2[2 * nt + 1]);
                    MMA16(ao[mt][nt], ah2[mt], bl2[2 * nt], bl2[2 * nt + 1]);
                    MMA16(ao[mt][nt], al2[mt], bh2[2 * nt], bh2[2 * nt + 1]);
                }
        }
        __syncthreads();
    }
#pragma unroll
    for (int mt = 0; mt < 2; mt++) {
        atomicAdd(&srs[wm * 32 + mt * 16 + (lane >> 2)], rs_[mt][0]);
        atomicAdd(&srs[wm * 32 + mt * 16 + (lane >> 2) + 8], rs_[mt][1]);
    }
    __syncthreads();
    if (tid < 64)
        rsp[((size_t)z * NHc + h) * Tc + t0 + tid] = srs[tid];
#pragma unroll
    for (int mt = 0; mt < 2; mt++)
#pragma unroll
        for (int nt = 0; nt < 2; nt++) {
            int tl = wm * 32 + mt * 16 + (lane >> 2);
            int d = wn * 16 + nt * 8 + 2 * (lane & 3);
            size_t b0 = (((size_t)z * NHc + h) * Tc + t0 + tl) * HDc + d;
            size_t b1 = (((size_t)z * NHc + h) * Tc + t0 + tl + 8) * HDc + d;
            aop[b0] = ao[mt][nt][0];
            aop[b0 + 1] = ao[mt][nt][1];
            aop[b1] = ao[mt][nt][2];
            aop[b1 + 1] = ao[mt][nt][3];
        }
}

// ---------------- host ----------------
extern "C" void kernel_launch(void* const* d_in, const int* in_sizes, int n_in,
                              void* d_out, int out_size) {
    const float *emb = 0, *kvk = 0, *kvv = 0, *pre_attn = 0, *wqkv = 0, *qnorm = 0,
                *knorm = 0, *wout = 0, *post_attn = 0, *pre_ff = 0, *wgate = 0,
                *wup = 0, *wdown = 0, *post_ff = 0, *finalw = 0, *wlm = 0,
                *cosg = 0, *sing = 0, *cosl = 0, *sinl = 0;
    int kv_n = 0, a = 0, b = 0, c = 0, d = 0;
    for (int i = 0; i < n_in; i++) {
        const float* p = (const float*)d_in[i];
        int s = in_sizes[i];
        if (s == 393216) emb = p;
        else if (s == 10223616) { if (kv_n++ == 0) kvk = p; else kvv = p; }
        else if (s == 19968) { if (a == 0) pre_attn = p; else if (a == 1) post_attn = p; else if (a == 2) pre_ff = p; else post_ff = p; a++; }
        else if (s == SZ_WQKV) wqkv = p;
        else if (s == 1664) { if (b++ == 0) qnorm = p; else knorm = p; }
        else if (s == SZ_WOUT) wout = p;
        else if (s == SZ_WFF) { if (c == 0) wgate = p; else if (c == 1) wup = p; else wdown = p; c++; }
        else if (s == 768) finalw = p;
        else if (s == SZ_WLM) wlm = p;
        else if (s == 32768) { if (d == 0) cosg = p; else if (d == 1) sing = p; else if (d == 2) cosl = p; else sinl = p; d++; }
    }
    float *ph, *pqkv, *pt1, *paop, *prsp, *pgp, *pup2;
    bf16 *pxh, *pxl, *path, *patl, *pgh, *pgl, *kh, *kl, *vh, *vl;
    bf16 *qkvh, *qkvl, *outh, *outl, *dnh, *dnl, *lmh, *lml, *gth, *gtl, *uph, *upl;
    cudaGetSymbolAddress((void**)&ph, g_h);
    cudaGetSymbolAddress((void**)&pqkv, g_qkv);
    cudaGetSymbolAddress((void**)&pt1, g_t1);
    cudaGetSymbolAddress((void**)&paop, g_aop);
    cudaGetSymbolAddress((void**)&prsp, g_rsp);
    cudaGetSymbolAddress((void**)&pgp, g_gp);
    cudaGetSymbolAddress((void**)&pup2, g_up2);
    cudaGetSymbolAddress((void**)&pxh, bx_h); cudaGetSymbolAddress((void**)&pxl, bx_l);
    cudaGetSymbolAddress((void**)&path, bat_h); cudaGetSymbolAddress((void**)&patl, bat_l);
    cudaGetSymbolAddress((void**)&pgh, bgt_h); cudaGetSymbolAddress((void**)&pgl, bgt_l);
    cudaGetSymbolAddress((void**)&kh, bk_h); cudaGetSymbolAddress((void**)&kl, bk_l);
    cudaGetSymbolAddress((void**)&vh, bv_h); cudaGetSymbolAddress((void**)&vl, bv_l);
    cudaGetSymbolAddress((void**)&qkvh, wqkv_h); cudaGetSymbolAddress((void**)&qkvl, wqkv_l);
    cudaGetSymbolAddress((void**)&outh, wout_h); cudaGetSymbolAddress((void**)&outl, wout_l);
    cudaGetSymbolAddress((void**)&gth, wgt_h); cudaGetSymbolAddress((void**)&gtl, wgt_l);
    cudaGetSymbolAddress((void**)&uph, wup_h); cudaGetSymbolAddress((void**)&upl, wup_l);
    cudaGetSymbolAddress((void**)&dnh, wdn_h); cudaGetSymbolAddress((void**)&dnl, wdn_l);
    cudaGetSymbolAddress((void**)&lmh, wlm_h); cudaGetSymbolAddress((void**)&lml, wlm_l);

    const int SM64 = (2 * 2 * 64 * 40 + 2 * 2 * 32 * 72) * 2;
    const int SM128 = (2 * 2 * 128 * 40 + 2 * 2 * 32 * 72) * 2;
    const int SMFF = (2 * 2 * 64 * 40 + 2 * 2 * 2 * 32 * 72) * 2;
    const int SMFL = 12 * 4608 * 2 + 64 * 4;

    cudaFuncSetAttribute(k_mm_t<64, 2>, cudaFuncAttributeMaxDynamicSharedMemorySize, SM64);
    cudaFuncSetAttribute(k_mm_t<128, 4>, cudaFuncAttributeMaxDynamicSharedMemorySize, SM128);
    cudaFuncSetAttribute(k_mmff, cudaFuncAttributeMaxDynamicSharedMemorySize, SMFF);
    cudaFuncSetAttribute(k_flash, cudaFuncAttributeMaxDynamicSharedMemorySize, SMFL);

    k_split4<<<SZ_WQKV / 4 / 256, 256>>>(wqkv, qkvh, qkvl, SZ_WQKV / 4);          // 0
    k_convall<<<Lc * 196608 / 256, 256>>>(kvk, kvv, kh, kl, vh, vl);              // 1
    k_init<<<Tc / 8, 256>>>(emb, pre_attn, ph, pxh, pxl);                         // 2

    for (int i = 0; i < Lc; i++) {
        int is_local = ((i + 1) % 6 == 0) ? 1 : 0;
        const float* cs = is_local ? cosl : cosg;
        const float* sn = is_local ? sinl : sing;
        bf16* khl = kh + (size_t)i * KVL;
        bf16* kll = kl + (size_t)i * KVL;
        bf16* vhl = vh + (size_t)i * KVL;
        bf16* vll = vl + (size_t)i * KVL;
        k_mm_t<64, 2><<<dim3(QKVW / 64, Tc / 64, 3), 256, SM64>>>(                 // 3
            pxh, pxl, qkvh + (size_t)i * Dc * QKVW, qkvl + (size_t)i * Dc * QKVW,
            pqkv, QKVW, Dc, (size_t)Tc * QKVW);
        k_qkprep<<<Tc * NGc / 8, 256>>>(pqkv, qnorm + i * HDc, knorm + i * HDc,    // 4
                                        cs, sn, khl, kll, vhl, vll);
        k_flash<<<dim3(Tc / 64, NHc, FZ), 256, SMFL>>>(khl, kll, vhl, vll,         // 5
                                                       paop, prsp, is_local);
        k_fcomb<<<NTD / 256, 256>>>(paop, prsp, path, patl);
        if (i == 0) {
            k_split4<<<SZ_WOUT / 4 / 256, 256>>>(wout, outh, outl, SZ_WOUT / 4);
            k_split4<<<SZ_WFF / 4 / 256, 256>>>(wgate, gth, gtl, SZ_WFF / 4);
            k_split4<<<SZ_WFF / 4 / 256, 256>>>(wup, uph, upl, SZ_WFF / 4);
            k_split4<<<SZ_WFF / 4 / 256, 256>>>(wdown, dnh, dnl, SZ_WFF / 4);
            k_split4<<<SZ_WLM / 4 / 256, 256>>>(wlm, lmh, lml, SZ_WLM / 4);
        }
        k_mm_t<64, 2><<<dim3(Dc / 64, Tc / 64, 3), 256, SM64>>>(
            path, patl, outh + (size_t)i * Dc * Dc, outl + (size_t)i * Dc * Dc,
            pt1, Dc, Dc, (size_t)Tc * Dc);
        k_fuse<<<Tc / 8, 256>>>(ph, pt1, 3, post_attn + i * Dc, pre_ff + i * Dc,
                                pxh, pxl);
        k_mmff<<<dim3(FFc / 64, Tc / 64, 3), 256, SMFF>>>(
            pxh, pxl,
            gth + (size_t)i * Dc * FFc, gtl + (size_t)i * Dc * FFc,
            uph + (size_t)i * Dc * FFc, upl + (size_t)i * Dc * FFc,
            pgp, pup2);
        k_gcomb<<<TF / 256, 256>>>(pgp, pup2, pgh, pgl);
        k_mm_t<64, 2><<<dim3(Dc / 64, Tc / 64, 4), 256, SM64>>>(
            pgh, pgl, dnh + (size_t)i * FFc * Dc, dnl + (size_t)i * FFc * Dc,
            pt1, Dc, FFc, (size_t)Tc * Dc);
        const float* wpre = (i + 1 < Lc) ? pre_attn + (i + 1) * Dc : finalw;
        k_fuse<<<Tc / 8, 256>>>(ph, pt1, 4, post_ff + i * Dc, wpre, pxh, pxl);
    }
    k_mm_t<128, 4><<<dim3(Vocab / 64, Tc / 128, 1), 256, SM128>>>(
        pxh, pxl, lmh, lml, (float*)d_out, Vocab, Dc, 0);
}

// round 14
// speedup vs baseline: 1.1803x; 1.1803x over previous
#include <cuda_runtime.h>
#include <cuda_bf16.h>
#include <math.h>
#include <stdint.h>

#define Lc 26
#define Tc 512
#define Dc 768
#define NHc 12
#define NGc 4
#define GSc 3
#define HDc 64
#define FFc 2048
#define CACHEc 1536
#define Sc 2048
#define Vocab 32000
#define WINc 512
#define QKVW 1280
typedef __nv_bfloat16 bf16;

#define SZ_WQKV 25559040
#define SZ_WOUT 15335424
#define SZ_WFF  40894464
#define SZ_WLM  24576000
#define KVL (NGc * Sc * HDc)
#define NTD (NHc * Tc * HDc)
#define FZ 3
#define TF (Tc * FFc)

// ---------------- scratch ----------------
__device__ float g_h[Tc * Dc];
__device__ float g_qkv[3 * Tc * QKVW];
__device__ float g_t1[4 * Tc * Dc];
__device__ float g_aop[FZ * NTD];
__device__ float g_rsp[FZ * NHc * Tc];
__device__ float g_gp[2 * TF];
__device__ float g_up2[2 * TF];
__device__ bf16 bx_h[Tc * Dc], bx_l[Tc * Dc];
__device__ bf16 bat_h[Tc * Dc], bat_l[Tc * Dc];
__device__ bf16 bgt_h[TF], bgt_l[TF];
__device__ bf16 bq_h[NTD], bq_l[NTD];
__device__ bf16 bk_h[Lc * KVL], bk_l[Lc * KVL];
__device__ bf16 bv_h[Lc * KVL], bv_l[Lc * KVL];
__device__ bf16 wqkv_h[SZ_WQKV], wqkv_l[SZ_WQKV];
__device__ bf16 wout_h[SZ_WOUT], wout_l[SZ_WOUT];
__device__ bf16 wgt_h[SZ_WFF], wgt_l[SZ_WFF];
__device__ bf16 wup_h[SZ_WFF], wup_l[SZ_WFF];
__device__ bf16 wdn_h[SZ_WFF], wdn_l[SZ_WFF];
__device__ bf16 wlm_h[SZ_WLM], wlm_l[SZ_WLM];

// ---------------- asm helpers ----------------
__device__ __forceinline__ uint32_t cvta(const void* p) {
    return (uint32_t)__cvta_generic_to_shared(p);
}
#define LDSM4(r, a) asm volatile( \
    "ldmatrix.sync.aligned.m8n8.x4.shared.b16 {%0,%1,%2,%3},[%4];\n" \
    : "=r"((r)[0]), "=r"((r)[1]), "=r"((r)[2]), "=r"((r)[3]) : "r"(a))
#define LDSM4T(r, a) asm volatile( \
    "ldmatrix.sync.aligned.m8n8.x4.trans.shared.b16 {%0,%1,%2,%3},[%4];\n" \
    : "=r"((r)[0]), "=r"((r)[1]), "=r"((r)[2]), "=r"((r)[3]) : "r"(a))
#define MMA16(c, a, b0, b1) asm volatile( \
    "mma.sync.aligned.m16n8k16.row.col.f32.bf16.bf16.f32 " \
    "{%0,%1,%2,%3},{%4,%5,%6,%7},{%8,%9},{%0,%1,%2,%3};\n" \
    : "+f"((c)[0]), "+f"((c)[1]), "+f"((c)[2]), "+f"((c)[3]) \
    : "r"((a)[0]), "r"((a)[1]), "r"((a)[2]), "r"((a)[3]), "r"(b0), "r"(b1))
#define CPA16(d, s) asm volatile("cp.async.cg.shared.global [%0],[%1],16;\n" :: "r"(d), "l"(s))
#define CPCOMMIT() asm volatile("cp.async.commit_group;\n")
#define CPWAIT(n) asm volatile("cp.async.wait_group %0;\n" :: "n"(n))

__device__ __forceinline__ void splitstore(bf16* ph, bf16* pl, size_t i, float v) {
    bf16 h = __float2bfloat16(v);
    ph[i] = h;
    pl[i] = __float2bfloat16(v - __bfloat162float(h));
}

__device__ __forceinline__ void split4v(float4 v, uint2& hi, uint2& lo) {
    __nv_bfloat162 h0, h1, l0, l1;
    h0.x = __float2bfloat16(v.x); h0.y = __float2bfloat16(v.y);
    h1.x = __float2bfloat16(v.z); h1.y = __float2bfloat16(v.w);
    l0.x = __float2bfloat16(v.x - __bfloat162float(h0.x));
    l0.y = __float2bfloat16(v.y - __bfloat162float(h0.y));
    l1.x = __float2bfloat16(v.z - __bfloat162float(h1.x));
    l1.y = __float2bfloat16(v.w - __bfloat162float(h1.y));
    hi.x = *(uint32_t*)&h0; hi.y = *(uint32_t*)&h1;
    lo.x = *(uint32_t*)&l0; lo.y = *(uint32_t*)&l1;
}

__device__ __forceinline__ float softcap_exp(float s) {
    float u = __expf(s * 0.005f);
    return __expf(50.f - 100.f / (u + 1.f));
}
__device__ __forceinline__ float fast_tanh(float y) {
    return 1.f - 2.f / (__expf(2.f * y) + 1.f);
}

__device__ __forceinline__ float blockReduceSum(float v) {
    __shared__ float sh[8];
    __syncthreads();
    int lane = threadIdx.x & 31, w = threadIdx.x >> 5;
#pragma unroll
    for (int o = 16; o; o >>= 1) v += __shfl_down_sync(0xffffffffu, v, o);
    if (lane == 0) sh[w] = v;
    __syncthreads();
    int nw = blockDim.x >> 5;
    if (w == 0) {
        v = (lane < nw) ? sh[lane] : 0.f;
#pragma unroll
        for (int o = 4; o; o >>= 1) v += __shfl_down_sync(0xffffffffu, v, o);
        if (lane == 0) sh[0] = v;
    }
    __syncthreads();
    return sh[0];
}

// ---------------- elementwise ----------------
__global__ void k_split4(const float* __restrict__ s, bf16* __restrict__ hi,
                         bf16* __restrict__ lo, int n4) {
    int i = blockIdx.x * blockDim.x + threadIdx.x;
    if (i >= n4) return;
    float4 v = ((const float4*)s)[i];
    uint2 h, l;
    split4v(v, h, l);
    ((uint2*)hi)[i] = h;
    ((uint2*)lo)[i] = l;
}

__global__ void k_convall(const float* __restrict__ ks, const float* __restrict__ vs,
                          bf16* __restrict__ kh, bf16* __restrict__ kl,
                          bf16* __restrict__ vh, bf16* __restrict__ vl) {
    int idx = blockIdx.x * blockDim.x + threadIdx.x;
    if (idx >= Lc * 196608) return;
    int layer = idx / 196608;
    int r = idx - layer * 196608;
    const float* ksl = ks + (size_t)layer * 393216;
    const float* vsl = vs + (size_t)layer * 393216;
    size_t kvoff = (size_t)layer * KVL;
    if (r < 98304) {
        int i4 = r * 4;
        int g = i4 / (CACHEc * HDc), rr = i4 - g * (CACHEc * HDc);
        size_t dst = kvoff + (size_t)g * Sc * HDc + rr;
        float4 v = ((const float4*)ksl)[r];
        uint2 h, l;
        split4v(v, h, l);
        *(uint2*)(kh + dst) = h;
        *(uint2*)(kl + dst) = l;
    } else {
        int j4 = (r - 98304) * 4;
        int row = j4 / CACHEc, c = j4 - row * CACHEc;
        size_t dst = kvoff + (size_t)row * Sc + c;
        float4 v = ((const float4*)vsl)[r - 98304];
        uint2 h, l;
        split4v(v, h, l);
        *(uint2*)(vh + dst) = h;
        *(uint2*)(vl + dst) = l;
    }
}

// block-per-row init
__global__ void k_init(const float* __restrict__ e, const float* __restrict__ w,
                       float* __restrict__ h, bf16* __restrict__ oh, bf16* __restrict__ ol) {
    int row = blockIdx.x;
    const float* x = e + (size_t)row * Dc;
    float ss = 0.f;
    for (int d = threadIdx.x; d < Dc; d += blockDim.x) { float v = x[d]; ss += v * v; }
    float rs = rsqrtf(blockReduceSum(ss) / Dc + 1e-6f);
    for (int d = threadIdx.x; d < Dc; d += blockDim.x) {
        float v = x[d];
        h[(size_t)row * Dc + d] = v;
        splitstore(oh, ol, (size_t)row * Dc + d, v * rs * (1.f + w[d]));
    }
}

// block-per-row: h += rmsnorm(sum_z t1[z], wpost); out = split(rmsnorm(h, wpre))
__global__ void k_fuse(float* __restrict__ h, const float* __restrict__ t1, int Z,
                       const float* __restrict__ wpost, const float* __restrict__ wpre,
                       bf16* __restrict__ oh, bf16* __restrict__ ol) {
    int row = blockIdx.x, tid = threadIdx.x;
    float x[3];
    float ss = 0.f;
#pragma unroll
    for (int i = 0; i < 3; i++) {
        int d = tid + i * 256;
        float v = 0.f;
        for (int z = 0; z < Z; z++) v += t1[(size_t)z * Tc * Dc + (size_t)row * Dc + d];
        x[i] = v;
        ss += v * v;
    }
    float rs = rsqrtf(blockReduceSum(ss) / Dc + 1e-6f);
    float hv[3];
    float ss2 = 0.f;
#pragma unroll
    for (int i = 0; i < 3; i++) {
        int d = tid + i * 256;
        float t = h[(size_t)row * Dc + d] + x[i] * rs * (1.f + wpost[d]);
        hv[i] = t;
        h[(size_t)row * Dc + d] = t;
        ss2 += t * t;
    }
    float rs2 = rsqrtf(blockReduceSum(ss2) / Dc + 1e-6f);
#pragma unroll
    for (int i = 0; i < 3; i++) {
        int d = tid + i * 256;
        splitstore(oh, ol, (size_t)row * Dc + d, hv[i] * rs2 * (1.f + wpre[d]));
    }
}

// block-per-(t,g) qkv prep: sum 3 split-K partials + head rmsnorm + rope + cache
__global__ void k_qkprep(const float* __restrict__ qkv,
                         const float* __restrict__ qw, const float* __restrict__ kw,
                         const float* __restrict__ cos_, const float* __restrict__ sin_,
                         bf16* __restrict__ kh, bf16* __restrict__ kl,
                         bf16* __restrict__ vh, bf16* __restrict__ vl) {
    int t = blockIdx.x, g = blockIdx.y, d = threadIdx.x;   // 64 threads
    size_t boff = ((size_t)(t * NGc + g) * (GSc + 2)) * HDc;
    const float* b0 = qkv + boff;
    const float* b1 = b0 + (size_t)Tc * QKVW;
    const float* b2 = b1 + (size_t)Tc * QKVW;
    __shared__ float sh[HDc];
    __shared__ float r2[2];
    float c = cos_[t * HDc + d], s = sin_[t * HDc + d];
#pragma unroll
    for (int j = 0; j <= GSc; j++) {
        int o = j * HDc + d;
        float v = b0[o] + b1[o] + b2[o];
        float sq = v * v;
#pragma unroll
        for (int of = 16; of; of >>= 1) sq += __shfl_down_sync(0xffffffffu, sq, of);
        if ((d & 31) == 0) r2[d >> 5] = sq;
        __syncthreads();
        float rs = rsqrtf((r2[0] + r2[1]) * (1.f / HDc) + 1e-6f);
        const float* wgt = (j < GSc) ? qw : kw;
        float nv = v * rs * (1.f + wgt[d]);
        sh[d] = nv;
        __syncthreads();
        float rot = (d < 32) ? -sh[d + 32] : sh[d - 32];
        float outv = nv * c + rot * s;
        if (j < GSc) splitstore(bq_h, bq_l, ((size_t)(g * GSc + j) * Tc + t) * HDc + d, outv);
        else splitstore(kh, kl, ((size_t)g * Sc + CACHEc + t) * HDc + d, outv);
        __syncthreads();
    }
    int vo = (GSc + 1) * HDc + d;
    float vv = b0[vo] + b1[vo] + b2[vo];
    splitstore(vh, vl, (size_t)(g * HDc + d) * Sc + CACHEc + t, vv);
}

__global__ void k_fcomb(const float* __restrict__ aop, const float* __restrict__ rsp,
                        bf16* __restrict__ oh, bf16* __restrict__ ol) {
    int i = blockIdx.x * blockDim.x + threadIdx.x;
    if (i >= NTD) return;
    int h = i / (Tc * HDc);
    int rem = i - h * (Tc * HDc);
    int t = rem / HDc, d = rem - (rem / HDc) * HDc;
    float r = 0.f, o = 0.f;
#pragma unroll
    for (int z = 0; z < FZ; z++) {
        r += rsp[((size_t)z * NHc + h) * Tc + t];
        o += aop[(size_t)z * NTD + i];
    }
    splitstore(oh, ol, (size_t)t * Dc + h * HDc + d, o / r);
}

// ff combine (2 partials): gelu(g)*(u) -> bf16 split
__global__ void k_gcomb(const float* __restrict__ gp, const float* __restrict__ up,
                        bf16* __restrict__ oh, bf16* __restrict__ ol) {
    int i = blockIdx.x * blockDim.x + threadIdx.x;
    if (i >= TF) return;
    float x = gp[i] + gp[TF + i];
    float u = up[i] + up[TF + i];
    float y = 0.7978845608028654f * (x + 0.044715f * x * x * x);
    splitstore(oh, ol, i, 0.5f * x * (1.f + fast_tanh(y)) * u);
}

// ============ templated GEMM: BM x 64 tile, BK=32, split-K via blockIdx.z ============
template <int BM, int WMW>
__global__ void __launch_bounds__(256) k_mm_t(const bf16* __restrict__ Ah,
                                              const bf16* __restrict__ Al,
                                              const bf16* __restrict__ Bh,
                                              const bf16* __restrict__ Bl,
                                              float* __restrict__ C, int N, int K,
                                              size_t cstride) {
    constexpr int WNW = 8 / WMW;
    constexpr int WROWS = BM / WMW;
    constexpr int WCOLS = 64 / WNW;
    constexpr int N8 = WCOLS / 8;
    constexpr int NB = WCOLS / 16;
    constexpr int AJ = BM / 64;
    extern __shared__ char dsm[];
    bf16* sA = (bf16*)dsm;
    bf16* sB = (bf16*)(dsm + 2 * 2 * BM * 40 * 2);
#define SAi(st, p, r, c) (sA + ((((st)*2 + (p)) * BM + (r)) * 40 + (c)))
#define SBi(st, p, r, c) (sB + ((((st)*2 + (p)) * 32 + (r)) * 72 + (c)))
    int z = blockIdx.z;
    int Ksub = K / gridDim.z;
    Ah += (size_t)z * Ksub;
    Al += (size_t)z * Ksub;
    Bh += (size_t)z * Ksub * N;
    Bl += (size_t)z * Ksub * N;
    C += (size_t)z * cstride;
    int tid = threadIdx.x, lane = tid & 31, warp = tid >> 5;
    int wm = warp % WMW, wn = warp / WMW;
    int bm = blockIdx.y * BM, bn = blockIdx.x * 64;
    int nIt = Ksub >> 5;
    int br = tid >> 3, bc = (tid & 7) << 3;
    const bf16* pBh = Bh + (size_t)br * N + bn + bc;
    const bf16* pBl = Bl + (size_t)br * N + bn + bc;
    float acc[2][N8][4] = {};
#pragma unroll
    for (int j = 0; j < AJ; j++) {
        int id = tid + j * 256, r = id >> 2, c = (id & 3) << 3;
        CPA16(cvta(SAi(0, 0, r, c)), Ah + (size_t)(bm + r) * K + c);
        CPA16(cvta(SAi(0, 1, r, c)), Al + (size_t)(bm + r) * K + c);
    }
    CPA16(cvta(SBi(0, 0, br, bc)), pBh);
    CPA16(cvta(SBi(0, 1, br, bc)), pBl);
    CPCOMMIT();
    for (int it = 0; it < nIt; it++) {
        int st = it & 1;
        if (it + 1 < nIt) {
            int k0 = (it + 1) << 5;
#pragma unroll
            for (int j = 0; j < AJ; j++) {
                int id = tid + j * 256, r = id >> 2, c = (id & 3) << 3;
                CPA16(cvta(SAi(st ^ 1, 0, r, c)), Ah + (size_t)(bm + r) * K + k0 + c);
                CPA16(cvta(SAi(st ^ 1, 1, r, c)), Al + (size_t)(bm + r) * K + k0 + c);
            }
            CPA16(cvta(SBi(st ^ 1, 0, br, bc)), pBh + (size_t)k0 * N);
            CPA16(cvta(SBi(st ^ 1, 1, br, bc)), pBl + (size_t)k0 * N);
            CPCOMMIT(); CPWAIT(1);
        } else CPWAIT(0);
        __syncthreads();
#pragma unroll
        for (int kp = 0; kp < 2; kp++) {
            uint32_t ah2[2][4], al2[2][4], bh2[4 * NB], bl2[4 * NB];
#pragma unroll
            for (int mt = 0; mt < 2; mt++) {
                int r = wm * WROWS + mt * 16 + (lane & 15), c = kp * 16 + ((lane >> 4) << 3);
                LDSM4(ah2[mt], cvta(SAi(st, 0, r, c)));
                LDSM4(al2[mt], cvta(SAi(st, 1, r, c)));
            }
            int bg = lane >> 3;
            int kr = kp * 16 + ((bg & 1) << 3) + (lane & 7);
#pragma unroll
            for (int nb = 0; nb < NB; nb++) {
                int nc = wn * WCOLS + nb * 16 + ((bg >> 1) << 3);
                LDSM4T(&bh2[nb * 4], cvta(SBi(st, 0, kr, nc)));
                LDSM4T(&bl2[nb * 4], cvta(SBi(st, 1, kr, nc)));
            }
#pragma unroll
            for (int mt = 0; mt < 2; mt++)
#pragma unroll
                for (int nt = 0; nt < N8; nt++) {
                    int f = (nt >> 1) * 4 + ((nt & 1) << 1);
                    MMA16(acc[mt][nt], ah2[mt], bh2[f], bh2[f + 1]);
                    MMA16(acc[mt][nt], ah2[mt], bl2[f], bl2[f + 1]);
                    MMA16(acc[mt][nt], al2[mt], bh2[f], bh2[f + 1]);
                }
        }
        __syncthreads();
    }
#pragma unroll
    for (int mt = 0; mt < 2; mt++)
#pragma unroll
        for (int nt = 0; nt < N8; nt++) {
            int r0 = bm + wm * WROWS + mt * 16 + (lane >> 2);
            int c0 = bn + wn * WCOLS + nt * 8 + 2 * (lane & 3);
            *(float2*)(C + (size_t)r0 * N + c0) = make_float2(acc[mt][nt][0], acc[mt][nt][1]);
            *(float2*)(C + (size_t)(r0 + 8) * N + c0) = make_float2(acc[mt][nt][2], acc[mt][nt][3]);
        }
#undef SAi
#undef SBi
}

// ============ dual GEMM (gate|up), split-K=2, fp32 partials ============
__global__ void __launch_bounds__(256) k_mmff(const bf16* __restrict__ Ah,
                                              const bf16* __restrict__ Al,
                                              const bf16* __restrict__ B0h,
                                              const bf16* __restrict__ B0l,
                                              const bf16* __restrict__ B1h,
                                              const bf16* __restrict__ B1l,
                                              float* __restrict__ Cg,
                                              float* __restrict__ Cu) {
    extern __shared__ char dsm[];
    bf16* sA = (bf16*)dsm;
    bf16* sB0 = (bf16*)(dsm + 2 * 2 * 64 * 40 * 2);
    bf16* sB1 = (bf16*)(dsm + 2 * 2 * 64 * 40 * 2 + 2 * 2 * 32 * 72 * 2);
#define SAi(st, p, r, c) (sA + ((((st)*2 + (p)) * 64 + (r)) * 40 + (c)))
#define SB0i(st, p, r, c) (sB0 + ((((st)*2 + (p)) * 32 + (r)) * 72 + (c)))
#define SB1i(st, p, r, c) (sB1 + ((((st)*2 + (p)) * 32 + (r)) * 72 + (c)))
    const int N = FFc, K = Dc;
    int z = blockIdx.z;
    int Ksub = K / gridDim.z;
    const bf16* Ahz = Ah + (size_t)z * Ksub;
    const bf16* Alz = Al + (size_t)z * Ksub;
    const bf16* B0hz = B0h + (size_t)z * Ksub * N;
    const bf16* B0lz = B0l + (size_t)z * Ksub * N;
    const bf16* B1hz = B1h + (size_t)z * Ksub * N;
    const bf16* B1lz = B1l + (size_t)z * Ksub * N;
    Cg += (size_t)z * TF;
    Cu += (size_t)z * TF;
    int tid = threadIdx.x, lane = tid & 31, warp = tid >> 5;
    int wm = warp & 1, wn = warp >> 1;
    int bm = blockIdx.y * 64, bn = blockIdx.x * 64;
    int br = tid >> 3, bc = (tid & 7) << 3;
    size_t boff = (size_t)br * N + bn + bc;
    float ag[2][2][4] = {}, au[2][2][4] = {};
    {
        int r = tid >> 2, c = (tid & 3) << 3;
        CPA16(cvta(SAi(0, 0, r, c)), Ahz + (size_t)(bm + r) * K + c);
        CPA16(cvta(SAi(0, 1, r, c)), Alz + (size_t)(bm + r) * K + c);
    }
    CPA16(cvta(SB0i(0, 0, br, bc)), B0hz + boff); CPA16(cvta(SB0i(0, 1, br, bc)), B0lz + boff);
    CPA16(cvta(SB1i(0, 0, br, bc)), B1hz + boff); CPA16(cvta(SB1i(0, 1, br, bc)), B1lz + boff);
    CPCOMMIT();
    int nIt = Ksub >> 5;
    for (int it = 0; it < nIt; it++) {
        int st = it & 1;
        if (it + 1 < nIt) {
            int k0 = (it + 1) << 5;
            int r = tid >> 2, c = (tid & 3) << 3;
            CPA16(cvta(SAi(st ^ 1, 0, r, c)), Ahz + (size_t)(bm + r) * K + k0 + c);
            CPA16(cvta(SAi(st ^ 1, 1, r, c)), Alz + (size_t)(bm + r) * K + k0 + c);
            CPA16(cvta(SB0i(st ^ 1, 0, br, bc)), B0hz + boff + (size_t)k0 * N);
            CPA16(cvta(SB0i(st ^ 1, 1, br, bc)), B0lz + boff + (size_t)k0 * N);
            CPA16(cvta(SB1i(st ^ 1, 0, br, bc)), B1hz + boff + (size_t)k0 * N);
            CPA16(cvta(SB1i(st ^ 1, 1, br, bc)), B1lz + boff + (size_t)k0 * N);
            CPCOMMIT(); CPWAIT(1);
        } else CPWAIT(0);
        __syncthreads();
#pragma unroll
        for (int kp = 0; kp < 2; kp++) {
            uint32_t ah2[2][4], al2[2][4], b0h[4], b0l[4], b1h[4], b1l[4];
#pragma unroll
            for (int mt = 0; mt < 2; mt++) {
                int r = wm * 32 + mt * 16 + (lane & 15), c = kp * 16 + ((lane >> 4) << 3);
                LDSM4(ah2[mt], cvta(SAi(st, 0, r, c)));
                LDSM4(al2[mt], cvta(SAi(st, 1, r, c)));
            }
            int bg = lane >> 3;
            int kr = kp * 16 + ((bg & 1) << 3) + (lane & 7);
            int nc = wn * 16 + ((bg >> 1) << 3);
            LDSM4T(b0h, cvta(SB0i(st, 0, kr, nc)));
            LDSM4T(b0l, cvta(SB0i(st, 1, kr, nc)));
            LDSM4T(b1h, cvta(SB1i(st, 0, kr, nc)));
            LDSM4T(b1l, cvta(SB1i(st, 1, kr, nc)));
#pragma unroll
            for (int mt = 0; mt < 2; mt++)
#pragma unroll
                for (int nt = 0; nt < 2; nt++) {
                    MMA16(ag[mt][nt], ah2[mt], b0h[2 * nt], b0h[2 * nt + 1]);
                    MMA16(ag[mt][nt], ah2[mt], b0l[2 * nt], b0l[2 * nt + 1]);
                    MMA16(ag[mt][nt], al2[mt], b0h[2 * nt], b0h[2 * nt + 1]);
                    MMA16(au[mt][nt], ah2[mt], b1h[2 * nt], b1h[2 * nt + 1]);
                    MMA16(au[mt][nt], ah2[mt], b1l[2 * nt], b1l[2 * nt + 1]);
                    MMA16(au[mt][nt], al2[mt], b1h[2 * nt], b1h[2 * nt + 1]);
                }
        }
        __syncthreads();
    }
#pragma unroll
    for (int mt = 0; mt < 2; mt++)
#pragma unroll
        for (int nt = 0; nt < 2; nt++) {
            int r0 = bm + wm * 32 + mt * 16 + (lane >> 2);
            int c0 = bn + wn * 16 + nt * 8 + 2 * (lane & 3);
            *(float2*)(Cg + (size_t)r0 * N + c0) = make_float2(ag[mt][nt][0], ag[mt][nt][1]);
            *(float2*)(Cg + (size_t)(r0 + 8) * N + c0) = make_float2(ag[mt][nt][2], ag[mt][nt][3]);
            *(float2*)(Cu + (size_t)r0 * N + c0) = make_float2(au[mt][nt][0], au[mt][nt][1]);
            *(float2*)(Cu + (size_t)(r0 + 8) * N + c0) = make_float2(au[mt][nt][2], au[mt][nt][3]);
        }
#undef SAi
#undef SB0i
#undef SB1i
}

// ============ flash attention: split-S partials, 2-stage KV pipeline ============
__global__ void __launch_bounds__(256) k_flash(const bf16* __restrict__ kh,
                                               const bf16* __restrict__ kl,
                                               const bf16* __restrict__ vhp,
                                               const bf16* __restrict__ vlp,
                                               float* __restrict__ aop,
                                               float* __restrict__ rsp,
                                               int is_local) {
    extern __shared__ char dsm[];
    bf16* sm = (bf16*)dsm;
    bf16* sQh = sm;
    bf16* sQl = sm + 4608;
    bf16* sKV[2][4];
    sKV[0][0] = sm + 2 * 4608; sKV[0][1] = sm + 3 * 4608;
    sKV[0][2] = sm + 4 * 4608; sKV[0][3] = sm + 5 * 4608;
    sKV[1][0] = sm + 6 * 4608; sKV[1][1] = sm + 7 * 4608;
    sKV[1][2] = sm + 8 * 4608; sKV[1][3] = sm + 9 * 4608;
    bf16* sPh = sm + 10 * 4608;
    bf16* sPl = sm + 11 * 4608;
    float* srs = (float*)(sm + 12 * 4608);
    int h = blockIdx.y, g = h / GSc, t0 = blockIdx.x * 64;
    int z = blockIdx.z;
    int tid = threadIdx.x, lane = tid & 31, warp = tid >> 5;
    int wm = warp & 1, wn = warp >> 1;
    const bf16* Qh_ = bq_h + ((size_t)h * Tc + t0) * HDc;
    const bf16* Ql_ = bq_l + ((size_t)h * Tc + t0) * HDc;
#pragma unroll
    for (int i = 0; i < 2; i++) {
        int c = tid + i * 256, r = c >> 3, cc = (c & 7) << 3;
        CPA16(cvta(sQh + r * 72 + cc), Qh_ + r * HDc + cc);
        CPA16(cvta(sQl + r * 72 + cc), Ql_ + r * HDc + cc);
    }
    if (tid < 64) srs[tid] = 0.f;
    float ao[2][2][4] = {};
    float rs_[2][2] = {};
    int s_lo = is_local ? ((CACHEc + t0 - WINc + 1) >> 6) : 0;
    int s_hi = (CACHEc + t0 + 63) >> 6;
    int nt_all = s_hi - s_lo + 1;
    int chunk = (nt_all + (int)gridDim.z - 1) / (int)gridDim.z;
    int my_lo = s_lo + z * chunk;
    int my_hi = my_lo + chunk - 1;
    if (my_hi > s_hi) my_hi = s_hi;

    auto loadkv = [&](int s0, int st) {
        const bf16* Kh_ = kh + ((size_t)g * Sc + s0) * HDc;
        const bf16* Kl_ = kl + ((size_t)g * Sc + s0) * HDc;
        const bf16* Vh_ = vhp + (size_t)g * HDc * Sc + s0;
        const bf16* Vl_ = vlp + (size_t)g * HDc * Sc + s0;
#pragma unroll
        for (int i = 0; i < 2; i++) {
            int c = tid + i * 256, r = c >> 3, cc = (c & 7) << 3;
            CPA16(cvta(sKV[st][0] + r * 72 + cc), Kh_ + r * HDc + cc);
            CPA16(cvta(sKV[st][1] + r * 72 + cc), Kl_ + r * HDc + cc);
            CPA16(cvta(sKV[st][2] + r * 72 + cc), Vh_ + (size_t)r * Sc + cc);
            CPA16(cvta(sKV[st][3] + r * 72 + cc), Vl_ + (size_t)r * Sc + cc);
        }
    };

    if (my_lo <= my_hi) loadkv(my_lo << 6, 0);
    CPCOMMIT();
    __syncthreads();

    for (int stile = my_lo; stile <= my_hi; stile++) {
        int st = (stile - my_lo) & 1;
        int s0 = stile << 6;
        if (stile < my_hi) {
            loadkv((stile + 1) << 6, st ^ 1);
            CPCOMMIT();
            CPWAIT(1);
        } else {
            CPWAIT(0);
        }
        __syncthreads();
        bf16 *cKh = sKV[st][0], *cKl = sKV[st][1], *cVh = sKV[st][2], *cVl = sKV[st][3];
        float sc_[2][2][4] = {};
#pragma unroll
        for (int kp = 0; kp < 4; kp++) {
            uint32_t ah2[2][4], al2[2][4], bh2[4], bl2[4];
#pragma unroll
            for (int mt = 0; mt < 2; mt++) {
                int r = wm * 32 + mt * 16 + (lane & 15), c = kp * 16 + ((lane >> 4) << 3);
                LDSM4(ah2[mt], cvta(sQh + r * 72 + c));
                LDSM4(al2[mt], cvta(sQl + r * 72 + c));
            }
            int bg = lane >> 3;
            int nr = wn * 16 + ((bg >> 1) << 3) + (lane & 7);
            int kc = kp * 16 + ((bg & 1) << 3);
            LDSM4(bh2, cvta(cKh + nr * 72 + kc));
            LDSM4(bl2, cvta(cKl + nr * 72 + kc));
#pragma unroll
            for (int mt = 0; mt < 2; mt++)
#pragma unroll
                for (int nt = 0; nt < 2; nt++) {
                    MMA16(sc_[mt][nt], ah2[mt], bh2[2 * nt], bh2[2 * nt + 1]);
                    MMA16(sc_[mt][nt], ah2[mt], bl2[2 * nt], bl2[2 * nt + 1]);
                    MMA16(sc_[mt][nt], al2[mt], bh2[2 * nt], bh2[2 * nt + 1]);
                }
        }
#pragma unroll
        for (int mt = 0; mt < 2; mt++)
#pragma unroll
            for (int nt = 0; nt < 2; nt++)
#pragma unroll
                for (int e = 0; e < 4; e++) {
                    int tl = wm * 32 + mt * 16 + (lane >> 2) + (e >= 2 ? 8 : 0);
                    int sl = wn * 16 + nt * 8 + 2 * (lane & 3) + (e & 1);
                    int sp = s0 + sl, qpos = CACHEc + t0 + tl;
                    bool ok = (sp <= qpos) && (!is_local || sp > qpos - WINc);
                    float p = ok ? softcap_exp(sc_[mt][nt][e]) : 0.f;
                    rs_[mt][e >= 2 ? 1 : 0] += p;
                    bf16 ph = __float2bfloat16(p);
                    sPh[tl * 72 + sl] = ph;
                    sPl[tl * 72 + sl] = __float2bfloat16(p - __bfloat162float(ph));
                }
        __syncthreads();
#pragma unroll
        for (int kp = 0; kp < 4; kp++) {
            uint32_t ah2[2][4], al2[2][4], bh2[4], bl2[4];
#pragma unroll
            for (int mt = 0; mt < 2; mt++) {
                int r = wm * 32 + mt * 16 + (lane & 15), c = kp * 16 + ((lane >> 4) << 3);
                LDSM4(ah2[mt], cvta(sPh + r * 72 + c));
                LDSM4(al2[mt], cvta(sPl + r * 72 + c));
            }
            int bg = lane >> 3;
            int nr = wn * 16 + ((bg >> 1) << 3) + (lane & 7);
            int kc = kp * 16 + ((bg & 1) << 3);
            LDSM4(bh2, cvta(cVh + nr * 72 + kc));
            LDSM4(bl2, cvta(cVl + nr * 72 + kc));
#pragma unroll
            for (int mt = 0; mt < 2; mt++)
#pragma unroll
                for (int nt = 0; nt < 2; nt++) {
                    MMA16(ao[mt][nt], ah2[mt], bh2[2 * nt], bh2[2 * nt + 1]);
                    MMA16(ao[mt][nt], ah2[mt], bl2[2 * nt], bl2[2 * nt + 1]);
                    MMA16(ao[mt][nt], al2[mt], bh2[2 * nt], bh2[2 * nt + 1]);
                }
        }
        __syncthreads();
    }
#pragma unroll
    for (int mt = 0; mt < 2; mt++) {
        atomicAdd(&srs[wm * 32 + mt * 16 + (lane >> 2)], rs_[mt][0]);
        atomicAdd(&srs[wm * 32 + mt * 16 + (lane >> 2) + 8], rs_[mt][1]);
    }
    __syncthreads();
    if (tid < 64)
        rsp[((size_t)z * NHc + h) * Tc + t0 + tid] = srs[tid];
#pragma unroll
    for (int mt = 0; mt < 2; mt++)
#pragma unroll
        for (int nt = 0; nt < 2; nt++) {
            int tl = wm * 32 + mt * 16 + (lane >> 2);
            int d = wn * 16 + nt * 8 + 2 * (lane & 3);
            size_t b0 = (((size_t)z * NHc + h) * Tc + t0 + tl) * HDc + d;
            size_t b1 = (((size_t)z * NHc + h) * Tc + t0 + tl + 8) * HDc + d;
            aop[b0] = ao[mt][nt][0];
            aop[b0 + 1] = ao[mt][nt][1];
            aop[b1] = ao[mt][nt][2];
            aop[b1 + 1] = ao[mt][nt][3];
        }
}

// ---------------- host ----------------
extern "C" void kernel_launch(void* const* d_in, const int* in_sizes, int n_in,
                              void* d_out, int out_size) {
    const float *emb = 0, *kvk = 0, *kvv = 0, *pre_attn = 0, *wqkv = 0, *qnorm = 0,
                *knorm = 0, *wout = 0, *post_attn = 0, *pre_ff = 0, *wgate = 0,
                *wup = 0, *wdown = 0, *post_ff = 0, *finalw = 0, *wlm = 0,
                *cosg = 0, *sing = 0, *cosl = 0, *sinl = 0;
    int kv_n = 0, a = 0, b = 0, c = 0, d = 0;
    for (int i = 0; i < n_in; i++) {
        const float* p = (const float*)d_in[i];
        int s = in_sizes[i];
        if (s == 393216) emb = p;
        else if (s == 10223616) { if (kv_n++ == 0) kvk = p; else kvv = p; }
        else if (s == 19968) { if (a == 0) pre_attn = p; else if (a == 1) post_attn = p; else if (a == 2) pre_ff = p; else post_ff = p; a++; }
        else if (s == SZ_WQKV) wqkv = p;
        else if (s == 1664) { if (b++ == 0) qnorm = p; else knorm = p; }
        else if (s == SZ_WOUT) wout = p;
        else if (s == SZ_WFF) { if (c == 0) wgate = p; else if (c == 1) wup = p; else wdown = p; c++; }
        else if (s == 768) finalw = p;
        else if (s == SZ_WLM) wlm = p;
        else if (s == 32768) { if (d == 0) cosg = p; else if (d == 1) sing = p; else if (d == 2) cosl = p; else sinl = p; d++; }
    }
    float *ph, *pqkv, *pt1, *paop, *prsp, *pgp, *pup2;
    bf16 *pxh, *pxl, *path, *patl, *pgh, *pgl, *kh, *kl, *vh, *vl;
    bf16 *qkvh, *qkvl, *outh, *outl, *dnh, *dnl, *lmh, *lml, *gth, *gtl, *uph, *upl;
    cudaGetSymbolAddress((void**)&ph, g_h);
    cudaGetSymbolAddress((void**)&pqkv, g_qkv);
    cudaGetSymbolAddress((void**)&pt1, g_t1);
    cudaGetSymbolAddress((void**)&paop, g_aop);
    cudaGetSymbolAddress((void**)&prsp, g_rsp);
    cudaGetSymbolAddress((void**)&pgp, g_gp);
    cudaGetSymbolAddress((void**)&pup2, g_up2);
    cudaGetSymbolAddress((void**)&pxh, bx_h); cudaGetSymbolAddress((void**)&pxl, bx_l);
    cudaGetSymbolAddress((void**)&path, bat_h); cudaGetSymbolAddress((void**)&patl, bat_l);
    cudaGetSymbolAddress((void**)&pgh, bgt_h); cudaGetSymbolAddress((void**)&pgl, bgt_l);
    cudaGetSymbolAddress((void**)&kh, bk_h); cudaGetSymbolAddress((void**)&kl, bk_l);
    cudaGetSymbolAddress((void**)&vh, bv_h); cudaGetSymbolAddress((void**)&vl, bv_l);
    cudaGetSymbolAddress((void**)&qkvh, wqkv_h); cudaGetSymbolAddress((void**)&qkvl, wqkv_l);
    cudaGetSymbolAddress((void**)&outh, wout_h); cudaGetSymbolAddress((void**)&outl, wout_l);
    cudaGetSymbolAddress((void**)&gth, wgt_h); cudaGetSymbolAddress((void**)&gtl, wgt_l);
    cudaGetSymbolAddress((void**)&uph, wup_h); cudaGetSymbolAddress((void**)&upl, wup_l);
    cudaGetSymbolAddress((void**)&dnh, wdn_h); cudaGetSymbolAddress((void**)&dnl, wdn_l);
    cudaGetSymbolAddress((void**)&lmh, wlm_h); cudaGetSymbolAddress((void**)&lml, wlm_l);

    const int SM64 = (2 * 2 * 64 * 40 + 2 * 2 * 32 * 72) * 2;
    const int SM128 = (2 * 2 * 128 * 40 + 2 * 2 * 32 * 72) * 2;
    const int SMFF = (2 * 2 * 64 * 40 + 2 * 2 * 2 * 32 * 72) * 2;
    const int SMFL = 12 * 4608 * 2 + 64 * 4;

    cudaFuncSetAttribute(k_mm_t<64, 2>, cudaFuncAttributeMaxDynamicSharedMemorySize, SM64);
    cudaFuncSetAttribute(k_mm_t<128, 4>, cudaFuncAttributeMaxDynamicSharedMemorySize, SM128);
    cudaFuncSetAttribute(k_mmff, cudaFuncAttributeMaxDynamicSharedMemorySize, SMFF);
    cudaFuncSetAttribute(k_flash, cudaFuncAttributeMaxDynamicSharedMemorySize, SMFL);

    k_split4<<<SZ_WQKV / 4 / 256, 256>>>(wqkv, qkvh, qkvl, SZ_WQKV / 4);          // 0
    k_convall<<<Lc * 196608 / 256, 256>>>(kvk, kvv, kh, kl, vh, vl);              // 1
    k_init<<<Tc, 256>>>(emb, pre_attn, ph, pxh, pxl);                             // 2

    for (int i = 0; i < Lc; i++) {
        int is_local = ((i + 1) % 6 == 0) ? 1 : 0;
        const float* cs = is_local ? cosl : cosg;
        const float* sn = is_local ? sinl : sing;
        bf16* khl = kh + (size_t)i * KVL;
        bf16* kll = kl + (size_t)i * KVL;
        bf16* vhl = vh + (size_t)i * KVL;
        bf16* vll = vl + (size_t)i * KVL;
        k_mm_t<64, 2><<<dim3(QKVW / 64, Tc / 64, 3), 256, SM64>>>(                 // 3
            pxh, pxl, qkvh + (size_t)i * Dc * QKVW, qkvl + (size_t)i * Dc * QKVW,
            pqkv, QKVW, Dc, (size_t)Tc * QKVW);
        k_qkprep<<<dim3(Tc, NGc), HDc>>>(pqkv, qnorm + i * HDc, knorm + i * HDc,   // 4
                                         cs, sn, khl, kll, vhl, vll);
        k_flash<<<dim3(Tc / 64, NHc, FZ), 256, SMFL>>>(khl, kll, vhl, vll,         // 5
                                                       paop, prsp, is_local);
        k_fcomb<<<NTD / 256, 256>>>(paop, prsp, path, patl);
        if (i == 0) {
            k_split4<<<SZ_WOUT / 4 / 256, 256>>>(wout, outh, outl, SZ_WOUT / 4);
            k_split4<<<SZ_WFF / 4 / 256, 256>>>(wgate, gth, gtl, SZ_WFF / 4);
            k_split4<<<SZ_WFF / 4 / 256, 256>>>(wup, uph, upl, SZ_WFF / 4);
            k_split4<<<SZ_WFF / 4 / 256, 256>>>(wdown, dnh, dnl, SZ_WFF / 4);
            k_split4<<<SZ_WLM / 4 / 256, 256>>>(wlm, lmh, lml, SZ_WLM / 4);
        }
        k_mm_t<64, 2><<<dim3(Dc / 64, Tc / 64, 3), 256, SM64>>>(
            path, patl, outh + (size_t)i * Dc * Dc, outl + (size_t)i * Dc * Dc,
            pt1, Dc, Dc, (size_t)Tc * Dc);
        k_fuse<<<Tc, 256>>>(ph, pt1, 3, post_attn + i * Dc, pre_ff + i * Dc,
                            pxh, pxl);
        k_mmff<<<dim3(FFc / 64, Tc / 64, 2), 256, SMFF>>>(
            pxh, pxl,
            gth + (size_t)i * Dc * FFc, gtl + (size_t)i * Dc * FFc,
            uph + (size_t)i * Dc * FFc, upl + (size_t)i * Dc * FFc,
            pgp, pup2);
        k_gcomb<<<TF / 256, 256>>>(pgp, pup2, pgh, pgl);
        k_mm_t<64, 2><<<dim3(Dc / 64, Tc / 64, 4), 256, SM64>>>(
            pgh, pgl, dnh + (size_t)i * FFc * Dc, dnl + (size_t)i * FFc * Dc,
            pt1, Dc, FFc, (size_t)Tc * Dc);
        const float* wpre = (i + 1 < Lc) ? pre_attn + (i + 1) * Dc : finalw;
        k_fuse<<<Tc, 256>>>(ph, pt1, 4, post_ff + i * Dc, wpre, pxh, pxl);
    }
    k_mm_t<128, 4><<<dim3(Vocab / 64, Tc / 128, 1), 256, SM128>>>(
        pxh, pxl, lmh, lml, (float*)d_out, Vocab, Dc, 0);
}

// round 15
// speedup vs baseline: 1.1814x; 1.0010x over previous
#include <cuda_runtime.h>
#include <cuda_bf16.h>
#include <math.h>
#include <stdint.h>

#define Lc 26
#define Tc 512
#define Dc 768
#define NHc 12
#define NGc 4
#define GSc 3
#define HDc 64
#define FFc 2048
#define CACHEc 1536
#define Sc 2048
#define Vocab 32000
#define WINc 512
#define QKVW 1280
typedef __nv_bfloat16 bf16;

#define SZ_WQKV 25559040
#define SZ_WOUT 15335424
#define SZ_WFF  40894464
#define SZ_WLM  24576000
#define KVL (NGc * Sc * HDc)
#define NTD (NHc * Tc * HDc)
#define FZ 3
#define TF (Tc * FFc)

// ---------------- scratch ----------------
__device__ float g_h[Tc * Dc];
__device__ float g_qkv[3 * Tc * QKVW];
__device__ float g_t1[4 * Tc * Dc];
__device__ float g_aop[FZ * NTD];
__device__ float g_rsp[FZ * NHc * Tc];
__device__ float g_gp[2 * TF];
__device__ float g_up2[2 * TF];
__device__ bf16 bx_h[Tc * Dc], bx_l[Tc * Dc];
__device__ bf16 bat_h[Tc * Dc], bat_l[Tc * Dc];
__device__ bf16 bgt_h[TF], bgt_l[TF];
__device__ bf16 bq_h[NTD], bq_l[NTD];
__device__ bf16 bk_h[Lc * KVL], bk_l[Lc * KVL];
__device__ bf16 bv_h[Lc * KVL], bv_l[Lc * KVL];
__device__ bf16 wqkv_h[SZ_WQKV], wqkv_l[SZ_WQKV];
__device__ bf16 wout_h[SZ_WOUT], wout_l[SZ_WOUT];
__device__ bf16 wgt_h[SZ_WFF], wgt_l[SZ_WFF];
__device__ bf16 wup_h[SZ_WFF], wup_l[SZ_WFF];
__device__ bf16 wdn_h[SZ_WFF], wdn_l[SZ_WFF];
__device__ bf16 wlm_h[SZ_WLM], wlm_l[SZ_WLM];

// ---------------- asm helpers ----------------
__device__ __forceinline__ uint32_t cvta(const void* p) {
    return (uint32_t)__cvta_generic_to_shared(p);
}
#define LDSM4(r, a) asm volatile( \
    "ldmatrix.sync.aligned.m8n8.x4.shared.b16 {%0,%1,%2,%3},[%4];\n" \
    : "=r"((r)[0]), "=r"((r)[1]), "=r"((r)[2]), "=r"((r)[3]) : "r"(a))
#define LDSM4T(r, a) asm volatile( \
    "ldmatrix.sync.aligned.m8n8.x4.trans.shared.b16 {%0,%1,%2,%3},[%4];\n" \
    : "=r"((r)[0]), "=r"((r)[1]), "=r"((r)[2]), "=r"((r)[3]) : "r"(a))
#define MMA16(c, a, b0, b1) asm volatile( \
    "mma.sync.aligned.m16n8k16.row.col.f32.bf16.bf16.f32 " \
    "{%0,%1,%2,%3},{%4,%5,%6,%7},{%8,%9},{%0,%1,%2,%3};\n" \
    : "+f"((c)[0]), "+f"((c)[1]), "+f"((c)[2]), "+f"((c)[3]) \
    : "r"((a)[0]), "r"((a)[1]), "r"((a)[2]), "r"((a)[3]), "r"(b0), "r"(b1))
#define CPA16(d, s) asm volatile("cp.async.cg.shared.global [%0],[%1],16;\n" :: "r"(d), "l"(s))
#define CPCOMMIT() asm volatile("cp.async.commit_group;\n")
#define CPWAIT(n) asm volatile("cp.async.wait_group %0;\n" :: "n"(n))

__device__ __forceinline__ void splitstore(bf16* ph, bf16* pl, size_t i, float v) {
    bf16 h = __float2bfloat16(v);
    ph[i] = h;
    pl[i] = __float2bfloat16(v - __bfloat162float(h));
}

__device__ __forceinline__ void split4v(float4 v, uint2& hi, uint2& lo) {
    __nv_bfloat162 h0, h1, l0, l1;
    h0.x = __float2bfloat16(v.x); h0.y = __float2bfloat16(v.y);
    h1.x = __float2bfloat16(v.z); h1.y = __float2bfloat16(v.w);
    l0.x = __float2bfloat16(v.x - __bfloat162float(h0.x));
    l0.y = __float2bfloat16(v.y - __bfloat162float(h0.y));
    l1.x = __float2bfloat16(v.z - __bfloat162float(h1.x));
    l1.y = __float2bfloat16(v.w - __bfloat162float(h1.y));
    hi.x = *(uint32_t*)&h0; hi.y = *(uint32_t*)&h1;
    lo.x = *(uint32_t*)&l0; lo.y = *(uint32_t*)&l1;
}

__device__ __forceinline__ float softcap_exp(float s) {
    float u = __expf(s * 0.005f);
    return __expf(50.f - 100.f / (u + 1.f));
}
__device__ __forceinline__ float fast_tanh(float y) {
    return 1.f - 2.f / (__expf(2.f * y) + 1.f);
}

__device__ __forceinline__ float blockReduceSum(float v) {
    __shared__ float sh[8];
    __syncthreads();
    int lane = threadIdx.x & 31, w = threadIdx.x >> 5;
#pragma unroll
    for (int o = 16; o; o >>= 1) v += __shfl_down_sync(0xffffffffu, v, o);
    if (lane == 0) sh[w] = v;
    __syncthreads();
    int nw = blockDim.x >> 5;
    if (w == 0) {
        v = (lane < nw) ? sh[lane] : 0.f;
#pragma unroll
        for (int o = 4; o; o >>= 1) v += __shfl_down_sync(0xffffffffu, v, o);
        if (lane == 0) sh[0] = v;
    }
    __syncthreads();
    return sh[0];
}

// ---------------- elementwise ----------------
__global__ void k_split4(const float* __restrict__ s, bf16* __restrict__ hi,
                         bf16* __restrict__ lo, int n4) {
    int i = blockIdx.x * blockDim.x + threadIdx.x;
    if (i >= n4) return;
    float4 v = ((const float4*)s)[i];
    uint2 h, l;
    split4v(v, h, l);
    ((uint2*)hi)[i] = h;
    ((uint2*)lo)[i] = l;
}

__global__ void k_convall(const float* __restrict__ ks, const float* __restrict__ vs,
                          bf16* __restrict__ kh, bf16* __restrict__ kl,
                          bf16* __restrict__ vh, bf16* __restrict__ vl) {
    int idx = blockIdx.x * blockDim.x + threadIdx.x;
    if (idx >= Lc * 196608) return;
    int layer = idx / 196608;
    int r = idx - layer * 196608;
    const float* ksl = ks + (size_t)layer * 393216;
    const float* vsl = vs + (size_t)layer * 393216;
    size_t kvoff = (size_t)layer * KVL;
    if (r < 98304) {
        int i4 = r * 4;
        int g = i4 / (CACHEc * HDc), rr = i4 - g * (CACHEc * HDc);
        size_t dst = kvoff + (size_t)g * Sc * HDc + rr;
        float4 v = ((const float4*)ksl)[r];
        uint2 h, l;
        split4v(v, h, l);
        *(uint2*)(kh + dst) = h;
        *(uint2*)(kl + dst) = l;
    } else {
        int j4 = (r - 98304) * 4;
        int row = j4 / CACHEc, c = j4 - row * CACHEc;
        size_t dst = kvoff + (size_t)row * Sc + c;
        float4 v = ((const float4*)vsl)[r - 98304];
        uint2 h, l;
        split4v(v, h, l);
        *(uint2*)(vh + dst) = h;
        *(uint2*)(vl + dst) = l;
    }
}

// block-per-row init
__global__ void k_init(const float* __restrict__ e, const float* __restrict__ w,
                       float* __restrict__ h, bf16* __restrict__ oh, bf16* __restrict__ ol) {
    int row = blockIdx.x;
    const float* x = e + (size_t)row * Dc;
    float ss = 0.f;
    for (int d = threadIdx.x; d < Dc; d += blockDim.x) { float v = x[d]; ss += v * v; }
    float rs = rsqrtf(blockReduceSum(ss) / Dc + 1e-6f);
    for (int d = threadIdx.x; d < Dc; d += blockDim.x) {
        float v = x[d];
        h[(size_t)row * Dc + d] = v;
        splitstore(oh, ol, (size_t)row * Dc + d, v * rs * (1.f + w[d]));
    }
}

// block-per-row: h += rmsnorm(sum_z t1[z], wpost); out = split(rmsnorm(h, wpre))
__global__ void k_fuse(float* __restrict__ h, const float* __restrict__ t1, int Z,
                       const float* __restrict__ wpost, const float* __restrict__ wpre,
                       bf16* __restrict__ oh, bf16* __restrict__ ol) {
    int row = blockIdx.x, tid = threadIdx.x;
    float x[3];
    float ss = 0.f;
#pragma unroll
    for (int i = 0; i < 3; i++) {
        int d = tid + i * 256;
        float v = 0.f;
        for (int z = 0; z < Z; z++) v += t1[(size_t)z * Tc * Dc + (size_t)row * Dc + d];
        x[i] = v;
        ss += v * v;
    }
    float rs = rsqrtf(blockReduceSum(ss) / Dc + 1e-6f);
    float hv[3];
    float ss2 = 0.f;
#pragma unroll
    for (int i = 0; i < 3; i++) {
        int d = tid + i * 256;
        float t = h[(size_t)row * Dc + d] + x[i] * rs * (1.f + wpost[d]);
        hv[i] = t;
        h[(size_t)row * Dc + d] = t;
        ss2 += t * t;
    }
    float rs2 = rsqrtf(blockReduceSum(ss2) / Dc + 1e-6f);
#pragma unroll
    for (int i = 0; i < 3; i++) {
        int d = tid + i * 256;
        splitstore(oh, ol, (size_t)row * Dc + d, hv[i] * rs2 * (1.f + wpre[d]));
    }
}

// block-per-(t,g) qkv prep: sum 3 split-K partials + head rmsnorm + rope + cache
__global__ void k_qkprep(const float* __restrict__ qkv,
                         const float* __restrict__ qw, const float* __restrict__ kw,
                         const float* __restrict__ cos_, const float* __restrict__ sin_,
                         bf16* __restrict__ kh, bf16* __restrict__ kl,
                         bf16* __restrict__ vh, bf16* __restrict__ vl) {
    int t = blockIdx.x, g = blockIdx.y, d = threadIdx.x;   // 64 threads
    size_t boff = ((size_t)(t * NGc + g) * (GSc + 2)) * HDc;
    const float* b0 = qkv + boff;
    const float* b1 = b0 + (size_t)Tc * QKVW;
    const float* b2 = b1 + (size_t)Tc * QKVW;
    __shared__ float sh[HDc];
    __shared__ float r2[2];
    float c = cos_[t * HDc + d], s = sin_[t * HDc + d];
#pragma unroll
    for (int j = 0; j <= GSc; j++) {
        int o = j * HDc + d;
        float v = b0[o] + b1[o] + b2[o];
        float sq = v * v;
#pragma unroll
        for (int of = 16; of; of >>= 1) sq += __shfl_down_sync(0xffffffffu, sq, of);
        if ((d & 31) == 0) r2[d >> 5] = sq;
        __syncthreads();
        float rs = rsqrtf((r2[0] + r2[1]) * (1.f / HDc) + 1e-6f);
        const float* wgt = (j < GSc) ? qw : kw;
        float nv = v * rs * (1.f + wgt[d]);
        sh[d] = nv;
        __syncthreads();
        float rot = (d < 32) ? -sh[d + 32] : sh[d - 32];
        float outv = nv * c + rot * s;
        if (j < GSc) splitstore(bq_h, bq_l, ((size_t)(g * GSc + j) * Tc + t) * HDc + d, outv);
        else splitstore(kh, kl, ((size_t)g * Sc + CACHEc + t) * HDc + d, outv);
        __syncthreads();
    }
    int vo = (GSc + 1) * HDc + d;
    float vv = b0[vo] + b1[vo] + b2[vo];
    splitstore(vh, vl, (size_t)(g * HDc + d) * Sc + CACHEc + t, vv);
}

__global__ void k_fcomb(const float* __restrict__ aop, const float* __restrict__ rsp,
                        bf16* __restrict__ oh, bf16* __restrict__ ol) {
    int i = blockIdx.x * blockDim.x + threadIdx.x;
    if (i >= NTD) return;
    int h = i / (Tc * HDc);
    int rem = i - h * (Tc * HDc);
    int t = rem / HDc, d = rem - (rem / HDc) * HDc;
    float r = 0.f, o = 0.f;
#pragma unroll
    for (int z = 0; z < FZ; z++) {
        r += rsp[((size_t)z * NHc + h) * Tc + t];
        o += aop[(size_t)z * NTD + i];
    }
    splitstore(oh, ol, (size_t)t * Dc + h * HDc + d, o / r);
}

// ff combine (2 partials): gelu(g)*(u) -> bf16 split
__global__ void k_gcomb(const float* __restrict__ gp, const float* __restrict__ up,
                        bf16* __restrict__ oh, bf16* __restrict__ ol) {
    int i = blockIdx.x * blockDim.x + threadIdx.x;
    if (i >= TF) return;
    float x = gp[i] + gp[TF + i];
    float u = up[i] + up[TF + i];
    float y = 0.7978845608028654f * (x + 0.044715f * x * x * x);
    splitstore(oh, ol, i, 0.5f * x * (1.f + fast_tanh(y)) * u);
}

// ============ templated GEMM: BM x 64 tile, BK=32, split-K via blockIdx.z ============
template <int BM, int WMW>
__global__ void __launch_bounds__(256) k_mm_t(const bf16* __restrict__ Ah,
                                              const bf16* __restrict__ Al,
                                              const bf16* __restrict__ Bh,
                                              const bf16* __restrict__ Bl,
                                              float* __restrict__ C, int N, int K,
                                              size_t cstride) {
    constexpr int WNW = 8 / WMW;
    constexpr int WROWS = BM / WMW;
    constexpr int WCOLS = 64 / WNW;
    constexpr int N8 = WCOLS / 8;
    constexpr int NB = WCOLS / 16;
    constexpr int AJ = BM / 64;
    extern __shared__ char dsm[];
    bf16* sA = (bf16*)dsm;
    bf16* sB = (bf16*)(dsm + 2 * 2 * BM * 40 * 2);
#define SAi(st, p, r, c) (sA + ((((st)*2 + (p)) * BM + (r)) * 40 + (c)))
#define SBi(st, p, r, c) (sB + ((((st)*2 + (p)) * 32 + (r)) * 72 + (c)))
    int z = blockIdx.z;
    int Ksub = K / gridDim.z;
    Ah += (size_t)z * Ksub;
    Al += (size_t)z * Ksub;
    Bh += (size_t)z * Ksub * N;
    Bl += (size_t)z * Ksub * N;
    C += (size_t)z * cstride;
    int tid = threadIdx.x, lane = tid & 31, warp = tid >> 5;
    int wm = warp % WMW, wn = warp / WMW;
    int bm = blockIdx.y * BM, bn = blockIdx.x * 64;
    int nIt = Ksub >> 5;
    int br = tid >> 3, bc = (tid & 7) << 3;
    const bf16* pBh = Bh + (size_t)br * N + bn + bc;
    const bf16* pBl = Bl + (size_t)br * N + bn + bc;
    float acc[2][N8][4] = {};
#pragma unroll
    for (int j = 0; j < AJ; j++) {
        int id = tid + j * 256, r = id >> 2, c = (id & 3) << 3;
        CPA16(cvta(SAi(0, 0, r, c)), Ah + (size_t)(bm + r) * K + c);
        CPA16(cvta(SAi(0, 1, r, c)), Al + (size_t)(bm + r) * K + c);
    }
    CPA16(cvta(SBi(0, 0, br, bc)), pBh);
    CPA16(cvta(SBi(0, 1, br, bc)), pBl);
    CPCOMMIT();
    for (int it = 0; it < nIt; it++) {
        int st = it & 1;
        if (it + 1 < nIt) {
            int k0 = (it + 1) << 5;
#pragma unroll
            for (int j = 0; j < AJ; j++) {
                int id = tid + j * 256, r = id >> 2, c = (id & 3) << 3;
                CPA16(cvta(SAi(st ^ 1, 0, r, c)), Ah + (size_t)(bm + r) * K + k0 + c);
                CPA16(cvta(SAi(st ^ 1, 1, r, c)), Al + (size_t)(bm + r) * K + k0 + c);
            }
            CPA16(cvta(SBi(st ^ 1, 0, br, bc)), pBh + (size_t)k0 * N);
            CPA16(cvta(SBi(st ^ 1, 1, br, bc)), pBl + (size_t)k0 * N);
            CPCOMMIT(); CPWAIT(1);
        } else CPWAIT(0);
        __syncthreads();
#pragma unroll
        for (int kp = 0; kp < 2; kp++) {
            uint32_t ah2[2][4], al2[2][4], bh2[4 * NB], bl2[4 * NB];
#pragma unroll
            for (int mt = 0; mt < 2; mt++) {
                int r = wm * WROWS + mt * 16 + (lane & 15), c = kp * 16 + ((lane >> 4) << 3);
                LDSM4(ah2[mt], cvta(SAi(st, 0, r, c)));
                LDSM4(al2[mt], cvta(SAi(st, 1, r, c)));
            }
            int bg = lane >> 3;
            int kr = kp * 16 + ((bg & 1) << 3) + (lane & 7);
#pragma unroll
            for (int nb = 0; nb < NB; nb++) {
                int nc = wn * WCOLS + nb * 16 + ((bg >> 1) << 3);
                LDSM4T(&bh2[nb * 4], cvta(SBi(st, 0, kr, nc)));
                LDSM4T(&bl2[nb * 4], cvta(SBi(st, 1, kr, nc)));
            }
#pragma unroll
            for (int mt = 0; mt < 2; mt++)
#pragma unroll
                for (int nt = 0; nt < N8; nt++) {
                    int f = (nt >> 1) * 4 + ((nt & 1) << 1);
                    MMA16(acc[mt][nt], ah2[mt], bh2[f], bh2[f + 1]);
                    MMA16(acc[mt][nt], ah2[mt], bl2[f], bl2[f + 1]);
                    MMA16(acc[mt][nt], al2[mt], bh2[f], bh2[f + 1]);
                }
        }
        __syncthreads();
    }
#pragma unroll
    for (int mt = 0; mt < 2; mt++)
#pragma unroll
        for (int nt = 0; nt < N8; nt++) {
            int r0 = bm + wm * WROWS + mt * 16 + (lane >> 2);
            int c0 = bn + wn * WCOLS + nt * 8 + 2 * (lane & 3);
            *(float2*)(C + (size_t)r0 * N + c0) = make_float2(acc[mt][nt][0], acc[mt][nt][1]);
            *(float2*)(C + (size_t)(r0 + 8) * N + c0) = make_float2(acc[mt][nt][2], acc[mt][nt][3]);
        }
#undef SAi
#undef SBi
}

// ============ dual GEMM (gate|up), split-K=2, fp32 partials ============
__global__ void __launch_bounds__(256) k_mmff(const bf16* __restrict__ Ah,
                                              const bf16* __restrict__ Al,
                                              const bf16* __restrict__ B0h,
                                              const bf16* __restrict__ B0l,
                                              const bf16* __restrict__ B1h,
                                              const bf16* __restrict__ B1l,
                                              float* __restrict__ Cg,
                                              float* __restrict__ Cu) {
    extern __shared__ char dsm[];
    bf16* sA = (bf16*)dsm;
    bf16* sB0 = (bf16*)(dsm + 2 * 2 * 64 * 40 * 2);
    bf16* sB1 = (bf16*)(dsm + 2 * 2 * 64 * 40 * 2 + 2 * 2 * 32 * 72 * 2);
#define SAi(st, p, r, c) (sA + ((((st)*2 + (p)) * 64 + (r)) * 40 + (c)))
#define SB0i(st, p, r, c) (sB0 + ((((st)*2 + (p)) * 32 + (r)) * 72 + (c)))
#define SB1i(st, p, r, c) (sB1 + ((((st)*2 + (p)) * 32 + (r)) * 72 + (c)))
    const int N = FFc, K = Dc;
    int z = blockIdx.z;
    int Ksub = K / gridDim.z;
    const bf16* Ahz = Ah + (size_t)z * Ksub;
    const bf16* Alz = Al + (size_t)z * Ksub;
    const bf16* B0hz = B0h + (size_t)z * Ksub * N;
    const bf16* B0lz = B0l + (size_t)z * Ksub * N;
    const bf16* B1hz = B1h + (size_t)z * Ksub * N;
    const bf16* B1lz = B1l + (size_t)z * Ksub * N;
    Cg += (size_t)z * TF;
    Cu += (size_t)z * TF;
    int tid = threadIdx.x, lane = tid & 31, warp = tid >> 5;
    int wm = warp & 1, wn = warp >> 1;
    int bm = blockIdx.y * 64, bn = blockIdx.x * 64;
    int br = tid >> 3, bc = (tid & 7) << 3;
    size_t boff = (size_t)br * N + bn + bc;
    float ag[2][2][4] = {}, au[2][2][4] = {};
    {
        int r = tid >> 2, c = (tid & 3) << 3;
        CPA16(cvta(SAi(0, 0, r, c)), Ahz + (size_t)(bm + r) * K + c);
        CPA16(cvta(SAi(0, 1, r, c)), Alz + (size_t)(bm + r) * K + c);
    }
    CPA16(cvta(SB0i(0, 0, br, bc)), B0hz + boff); CPA16(cvta(SB0i(0, 1, br, bc)), B0lz + boff);
    CPA16(cvta(SB1i(0, 0, br, bc)), B1hz + boff); CPA16(cvta(SB1i(0, 1, br, bc)), B1lz + boff);
    CPCOMMIT();
    int nIt = Ksub >> 5;
    for (int it = 0; it < nIt; it++) {
        int st = it & 1;
        if (it + 1 < nIt) {
            int k0 = (it + 1) << 5;
            int r = tid >> 2, c = (tid & 3) << 3;
            CPA16(cvta(SAi(st ^ 1, 0, r, c)), Ahz + (size_t)(bm + r) * K + k0 + c);
            CPA16(cvta(SAi(st ^ 1, 1, r, c)), Alz + (size_t)(bm + r) * K + k0 + c);
            CPA16(cvta(SB0i(st ^ 1, 0, br, bc)), B0hz + boff + (size_t)k0 * N);
            CPA16(cvta(SB0i(st ^ 1, 1, br, bc)), B0lz + boff + (size_t)k0 * N);
            CPA16(cvta(SB1i(st ^ 1, 0, br, bc)), B1hz + boff + (size_t)k0 * N);
            CPA16(cvta(SB1i(st ^ 1, 1, br, bc)), B1lz + boff + (size_t)k0 * N);
            CPCOMMIT(); CPWAIT(1);
        } else CPWAIT(0);
        __syncthreads();
#pragma unroll
        for (int kp = 0; kp < 2; kp++) {
            uint32_t ah2[2][4], al2[2][4], b0h[4], b0l[4], b1h[4], b1l[4];
#pragma unroll
            for (int mt = 0; mt < 2; mt++) {
                int r = wm * 32 + mt * 16 + (lane & 15), c = kp * 16 + ((lane >> 4) << 3);
                LDSM4(ah2[mt], cvta(SAi(st, 0, r, c)));
                LDSM4(al2[mt], cvta(SAi(st, 1, r, c)));
            }
            int bg = lane >> 3;
            int kr = kp * 16 + ((bg & 1) << 3) + (lane & 7);
            int nc = wn * 16 + ((bg >> 1) << 3);
            LDSM4T(b0h, cvta(SB0i(st, 0, kr, nc)));
            LDSM4T(b0l, cvta(SB0i(st, 1, kr, nc)));
            LDSM4T(b1h, cvta(SB1i(st, 0, kr, nc)));
            LDSM4T(b1l, cvta(SB1i(st, 1, kr, nc)));
#pragma unroll
            for (int mt = 0; mt < 2; mt++)
#pragma unroll
                for (int nt = 0; nt < 2; nt++) {
                    MMA16(ag[mt][nt], ah2[mt], b0h[2 * nt], b0h[2 * nt + 1]);
                    MMA16(ag[mt][nt], ah2[mt], b0l[2 * nt], b0l[2 * nt + 1]);
                    MMA16(ag[mt][nt], al2[mt], b0h[2 * nt], b0h[2 * nt + 1]);
                    MMA16(au[mt][nt], ah2[mt], b1h[2 * nt], b1h[2 * nt + 1]);
                    MMA16(au[mt][nt], ah2[mt], b1l[2 * nt], b1l[2 * nt + 1]);
                    MMA16(au[mt][nt], al2[mt], b1h[2 * nt], b1h[2 * nt + 1]);
                }
        }
        __syncthreads();
    }
#pragma unroll
    for (int mt = 0; mt < 2; mt++)
#pragma unroll
        for (int nt = 0; nt < 2; nt++) {
            int r0 = bm + wm * 32 + mt * 16 + (lane >> 2);
            int c0 = bn + wn * 16 + nt * 8 + 2 * (lane & 3);
            *(float2*)(Cg + (size_t)r0 * N + c0) = make_float2(ag[mt][nt][0], ag[mt][nt][1]);
            *(float2*)(Cg + (size_t)(r0 + 8) * N + c0) = make_float2(ag[mt][nt][2], ag[mt][nt][3]);
            *(float2*)(Cu + (size_t)r0 * N + c0) = make_float2(au[mt][nt][0], au[mt][nt][1]);
            *(float2*)(Cu + (size_t)(r0 + 8) * N + c0) = make_float2(au[mt][nt][2], au[mt][nt][3]);
        }
#undef SAi
#undef SB0i
#undef SB1i
}

// ============ flash attention: split-S partials, 2-stage KV pipeline ============
__global__ void __launch_bounds__(256) k_flash(const bf16* __restrict__ kh,
                                               const bf16* __restrict__ kl,
                                               const bf16* __restrict__ vhp,
                                               const bf16* __restrict__ vlp,
                                               float* __restrict__ aop,
                                               float* __restrict__ rsp,
                                               int is_local) {
    extern __shared__ char dsm[];
    bf16* sm = (bf16*)dsm;
    bf16* sQh = sm;
    bf16* sQl = sm + 4608;
    bf16* sKV[2][4];
    sKV[0][0] = sm + 2 * 4608; sKV[0][1] = sm + 3 * 4608;
    sKV[0][2] = sm + 4 * 4608; sKV[0][3] = sm + 5 * 4608;
    sKV[1][0] = sm + 6 * 4608; sKV[1][1] = sm + 7 * 4608;
    sKV[1][2] = sm + 8 * 4608; sKV[1][3] = sm + 9 * 4608;
    bf16* sPh = sm + 10 * 4608;
    bf16* sPl = sm + 11 * 4608;
    float* srs = (float*)(sm + 12 * 4608);
    int h = blockIdx.y, g = h / GSc, t0 = blockIdx.x * 64;
    int z = blockIdx.z;
    int tid = threadIdx.x, lane = tid & 31, warp = tid >> 5;
    int wm = warp & 1, wn = warp >> 1;
    const bf16* Qh_ = bq_h + ((size_t)h * Tc + t0) * HDc;
    const bf16* Ql_ = bq_l + ((size_t)h * Tc + t0) * HDc;
#pragma unroll
    for (int i = 0; i < 2; i++) {
        int c = tid + i * 256, r = c >> 3, cc = (c & 7) << 3;
        CPA16(cvta(sQh + r * 72 + cc), Qh_ + r * HDc + cc);
        CPA16(cvta(sQl + r * 72 + cc), Ql_ + r * HDc + cc);
    }
    if (tid < 64) srs[tid] = 0.f;
    float ao[2][2][4] = {};
    float rs_[2][2] = {};
    int s_lo = is_local ? ((CACHEc + t0 - WINc + 1) >> 6) : 0;
    int s_hi = (CACHEc + t0 + 63) >> 6;
    int nt_all = s_hi - s_lo + 1;
    int chunk = (nt_all + (int)gridDim.z - 1) / (int)gridDim.z;
    int my_lo = s_lo + z * chunk;
    int my_hi = my_lo + chunk - 1;
    if (my_hi > s_hi) my_hi = s_hi;

    auto loadkv = [&](int s0, int st) {
        const bf16* Kh_ = kh + ((size_t)g * Sc + s0) * HDc;
        const bf16* Kl_ = kl + ((size_t)g * Sc + s0) * HDc;
        const bf16* Vh_ = vhp + (size_t)g * HDc * Sc + s0;
        const bf16* Vl_ = vlp + (size_t)g * HDc * Sc + s0;
#pragma unroll
        for (int i = 0; i < 2; i++) {
            int c = tid + i * 256, r = c >> 3, cc = (c & 7) << 3;
            CPA16(cvta(sKV[st][0] + r * 72 + cc), Kh_ + r * HDc + cc);
            CPA16(cvta(sKV[st][1] + r * 72 + cc), Kl_ + r * HDc + cc);
            CPA16(cvta(sKV[st][2] + r * 72 + cc), Vh_ + (size_t)r * Sc + cc);
            CPA16(cvta(sKV[st][3] + r * 72 + cc), Vl_ + (size_t)r * Sc + cc);
        }
    };

    if (my_lo <= my_hi) loadkv(my_lo << 6, 0);
    CPCOMMIT();
    __syncthreads();

    for (int stile = my_lo; stile <= my_hi; stile++) {
        int st = (stile - my_lo) & 1;
        int s0 = stile << 6;
        if (stile < my_hi) {
            loadkv((stile + 1) << 6, st ^ 1);
            CPCOMMIT();
            CPWAIT(1);
        } else {
            CPWAIT(0);
        }
        __syncthreads();
        bf16 *cKh = sKV[st][0], *cKl = sKV[st][1], *cVh = sKV[st][2], *cVl = sKV[st][3];
        float sc_[2][2][4] = {};
#pragma unroll
        for (int kp = 0; kp < 4; kp++) {
            uint32_t ah2[2][4], al2[2][4], bh2[4], bl2[4];
#pragma unroll
            for (int mt = 0; mt < 2; mt++) {
                int r = wm * 32 + mt * 16 + (lane & 15), c = kp * 16 + ((lane >> 4) << 3);
                LDSM4(ah2[mt], cvta(sQh + r * 72 + c));
                LDSM4(al2[mt], cvta(sQl + r * 72 + c));
            }
            int bg = lane >> 3;
            int nr = wn * 16 + ((bg >> 1) << 3) + (lane & 7);
            int kc = kp * 16 + ((bg & 1) << 3);
            LDSM4(bh2, cvta(cKh + nr * 72 + kc));
            LDSM4(bl2, cvta(cKl + nr * 72 + kc));
#pragma unroll
            for (int mt = 0; mt < 2; mt++)
#pragma unroll
                for (int nt = 0; nt < 2; nt++) {
                    MMA16(sc_[mt][nt], ah2[mt], bh2[2 * nt], bh2[2 * nt + 1]);
                    MMA16(sc_[mt][nt], ah2[mt], bl2[2 * nt], bl2[2 * nt + 1]);
                    MMA16(sc_[mt][nt], al2[mt], bh2[2 * nt], bh2[2 * nt + 1]);
                }
        }
#pragma unroll
        for (int mt = 0; mt < 2; mt++)
#pragma unroll
            for (int nt = 0; nt < 2; nt++)
#pragma unroll
                for (int e = 0; e < 4; e++) {
                    int tl = wm * 32 + mt * 16 + (lane >> 2) + (e >= 2 ? 8 : 0);
                    int sl = wn * 16 + nt * 8 + 2 * (lane & 3) + (e & 1);
                    int sp = s0 + sl, qpos = CACHEc + t0 + tl;
                    bool ok = (sp <= qpos) && (!is_local || sp > qpos - WINc);
                    float p = ok ? softcap_exp(sc_[mt][nt][e]) : 0.f;
                    rs_[mt][e >= 2 ? 1 : 0] += p;
                    bf16 ph = __float2bfloat16(p);
                    sPh[tl * 72 + sl] = ph;
                    sPl[tl * 72 + sl] = __float2bfloat16(p - __bfloat162float(ph));
                }
        __syncthreads();
#pragma unroll
        for (int kp = 0; kp < 4; kp++) {
            uint32_t ah2[2][4], al2[2][4], bh2[4], bl2[4];
#pragma unroll
            for (int mt = 0; mt < 2; mt++) {
                int r = wm * 32 + mt * 16 + (lane & 15), c = kp * 16 + ((lane >> 4) << 3);
                LDSM4(ah2[mt], cvta(sPh + r * 72 + c));
                LDSM4(al2[mt], cvta(sPl + r * 72 + c));
            }
            int bg = lane >> 3;
            int nr = wn * 16 + ((bg >> 1) << 3) + (lane & 7);
            int kc = kp * 16 + ((bg & 1) << 3);
            LDSM4(bh2, cvta(cVh + nr * 72 + kc));
            LDSM4(bl2, cvta(cVl + nr * 72 + kc));
#pragma unroll
            for (int mt = 0; mt < 2; mt++)
#pragma unroll
                for (int nt = 0; nt < 2; nt++) {
                    MMA16(ao[mt][nt], ah2[mt], bh2[2 * nt], bh2[2 * nt + 1]);
                    MMA16(ao[mt][nt], ah2[mt], bl2[2 * nt], bl2[2 * nt + 1]);
                    MMA16(ao[mt][nt], al2[mt], bh2[2 * nt], bh2[2 * nt + 1]);
                }
        }
        __syncthreads();
    }
#pragma unroll
    for (int mt = 0; mt < 2; mt++) {
        atomicAdd(&srs[wm * 32 + mt * 16 + (lane >> 2)], rs_[mt][0]);
        atomicAdd(&srs[wm * 32 + mt * 16 + (lane >> 2) + 8], rs_[mt][1]);
    }
    __syncthreads();
    if (tid < 64)
        rsp[((size_t)z * NHc + h) * Tc + t0 + tid] = srs[tid];
#pragma unroll
    for (int mt = 0; mt < 2; mt++)
#pragma unroll
        for (int nt = 0; nt < 2; nt++) {
            int tl = wm * 32 + mt * 16 + (lane >> 2);
            int d = wn * 16 + nt * 8 + 2 * (lane & 3);
            size_t b0 = (((size_t)z * NHc + h) * Tc + t0 + tl) * HDc + d;
            size_t b1 = (((size_t)z * NHc + h) * Tc + t0 + tl + 8) * HDc + d;
            aop[b0] = ao[mt][nt][0];
            aop[b0 + 1] = ao[mt][nt][1];
            aop[b1] = ao[mt][nt][2];
            aop[b1 + 1] = ao[mt][nt][3];
        }
}

// ---------------- host ----------------
extern "C" void kernel_launch(void* const* d_in, const int* in_sizes, int n_in,
                              void* d_out, int out_size) {
    const float *emb = 0, *kvk = 0, *kvv = 0, *pre_attn = 0, *wqkv = 0, *qnorm = 0,
                *knorm = 0, *wout = 0, *post_attn = 0, *pre_ff = 0, *wgate = 0,
                *wup = 0, *wdown = 0, *post_ff = 0, *finalw = 0, *wlm = 0,
                *cosg = 0, *sing = 0, *cosl = 0, *sinl = 0;
    int kv_n = 0, a = 0, b = 0, c = 0, d = 0;
    for (int i = 0; i < n_in; i++) {
        const float* p = (const float*)d_in[i];
        int s = in_sizes[i];
        if (s == 393216) emb = p;
        else if (s == 10223616) { if (kv_n++ == 0) kvk = p; else kvv = p; }
        else if (s == 19968) { if (a == 0) pre_attn = p; else if (a == 1) post_attn = p; else if (a == 2) pre_ff = p; else post_ff = p; a++; }
        else if (s == SZ_WQKV) wqkv = p;
        else if (s == 1664) { if (b++ == 0) qnorm = p; else knorm = p; }
        else if (s == SZ_WOUT) wout = p;
        else if (s == SZ_WFF) { if (c == 0) wgate = p; else if (c == 1) wup = p; else wdown = p; c++; }
        else if (s == 768) finalw = p;
        else if (s == SZ_WLM) wlm = p;
        else if (s == 32768) { if (d == 0) cosg = p; else if (d == 1) sing = p; else if (d == 2) cosl = p; else sinl = p; d++; }
    }
    float *ph, *pqkv, *pt1, *paop, *prsp, *pgp, *pup2;
    bf16 *pxh, *pxl, *path, *patl, *pgh, *pgl, *kh, *kl, *vh, *vl;
    bf16 *qkvh, *qkvl, *outh, *outl, *dnh, *dnl, *lmh, *lml, *gth, *gtl, *uph, *upl;
    cudaGetSymbolAddress((void**)&ph, g_h);
    cudaGetSymbolAddress((void**)&pqkv, g_qkv);
    cudaGetSymbolAddress((void**)&pt1, g_t1);
    cudaGetSymbolAddress((void**)&paop, g_aop);
    cudaGetSymbolAddress((void**)&prsp, g_rsp);
    cudaGetSymbolAddress((void**)&pgp, g_gp);
    cudaGetSymbolAddress((void**)&pup2, g_up2);
    cudaGetSymbolAddress((void**)&pxh, bx_h); cudaGetSymbolAddress((void**)&pxl, bx_l);
    cudaGetSymbolAddress((void**)&path, bat_h); cudaGetSymbolAddress((void**)&patl, bat_l);
    cudaGetSymbolAddress((void**)&pgh, bgt_h); cudaGetSymbolAddress((void**)&pgl, bgt_l);
    cudaGetSymbolAddress((void**)&kh, bk_h); cudaGetSymbolAddress((void**)&kl, bk_l);
    cudaGetSymbolAddress((void**)&vh, bv_h); cudaGetSymbolAddress((void**)&vl, bv_l);
    cudaGetSymbolAddress((void**)&qkvh, wqkv_h); cudaGetSymbolAddress((void**)&qkvl, wqkv_l);
    cudaGetSymbolAddress((void**)&outh, wout_h); cudaGetSymbolAddress((void**)&outl, wout_l);
    cudaGetSymbolAddress((void**)&gth, wgt_h); cudaGetSymbolAddress((void**)&gtl, wgt_l);
    cudaGetSymbolAddress((void**)&uph, wup_h); cudaGetSymbolAddress((void**)&upl, wup_l);
    cudaGetSymbolAddress((void**)&dnh, wdn_h); cudaGetSymbolAddress((void**)&dnl, wdn_l);
    cudaGetSymbolAddress((void**)&lmh, wlm_h); cudaGetSymbolAddress((void**)&lml, wlm_l);

    const int SM64 = (2 * 2 * 64 * 40 + 2 * 2 * 32 * 72) * 2;
    const int SM128 = (2 * 2 * 128 * 40 + 2 * 2 * 32 * 72) * 2;
    const int SMFF = (2 * 2 * 64 * 40 + 2 * 2 * 2 * 32 * 72) * 2;
    const int SMFL = 12 * 4608 * 2 + 64 * 4;

    cudaFuncSetAttribute(k_mm_t<64, 2>, cudaFuncAttributeMaxDynamicSharedMemorySize, SM64);
    cudaFuncSetAttribute(k_mm_t<128, 4>, cudaFuncAttributeMaxDynamicSharedMemorySize, SM128);
    cudaFuncSetAttribute(k_mmff, cudaFuncAttributeMaxDynamicSharedMemorySize, SMFF);
    cudaFuncSetAttribute(k_flash, cudaFuncAttributeMaxDynamicSharedMemorySize, SMFL);

    // side stream + events (created once; no device memory involved)
    static cudaStream_t s2 = 0;
    static cudaEvent_t evFork = 0, evKV = 0, evOut = 0, evFF = 0, evDn = 0, evLM = 0;
    if (!s2) {
        cudaStreamCreateWithFlags(&s2, cudaStreamNonBlocking);
        cudaEventCreateWithFlags(&evFork, cudaEventDisableTiming);
        cudaEventCreateWithFlags(&evKV, cudaEventDisableTiming);
        cudaEventCreateWithFlags(&evOut, cudaEventDisableTiming);
        cudaEventCreateWithFlags(&evFF, cudaEventDisableTiming);
        cudaEventCreateWithFlags(&evDn, cudaEventDisableTiming);
        cudaEventCreateWithFlags(&evLM, cudaEventDisableTiming);
    }

    // fork: side stream does KV conversion + deferred weight splits
    cudaEventRecord(evFork, 0);
    cudaStreamWaitEvent(s2, evFork, 0);
    k_convall<<<Lc * 196608 / 256, 256, 0, s2>>>(kvk, kvv, kh, kl, vh, vl);
    cudaEventRecord(evKV, s2);
    k_split4<<<SZ_WOUT / 4 / 256, 256, 0, s2>>>(wout, outh, outl, SZ_WOUT / 4);
    cudaEventRecord(evOut, s2);
    k_split4<<<SZ_WFF / 4 / 256, 256, 0, s2>>>(wgate, gth, gtl, SZ_WFF / 4);
    k_split4<<<SZ_WFF / 4 / 256, 256, 0, s2>>>(wup, uph, upl, SZ_WFF / 4);
    cudaEventRecord(evFF, s2);
    k_split4<<<SZ_WFF / 4 / 256, 256, 0, s2>>>(wdown, dnh, dnl, SZ_WFF / 4);
    cudaEventRecord(evDn, s2);
    k_split4<<<SZ_WLM / 4 / 256, 256, 0, s2>>>(wlm, lmh, lml, SZ_WLM / 4);
    cudaEventRecord(evLM, s2);

    // main stream
    k_split4<<<SZ_WQKV / 4 / 256, 256>>>(wqkv, qkvh, qkvl, SZ_WQKV / 4);
    k_init<<<Tc, 256>>>(emb, pre_attn, ph, pxh, pxl);

    for (int i = 0; i < Lc; i++) {
        int is_local = ((i + 1) % 6 == 0) ? 1 : 0;
        const float* cs = is_local ? cosl : cosg;
        const float* sn = is_local ? sinl : sing;
        bf16* khl = kh + (size_t)i * KVL;
        bf16* kll = kl + (size_t)i * KVL;
        bf16* vhl = vh + (size_t)i * KVL;
        bf16* vll = vl + (size_t)i * KVL;
        k_mm_t<64, 2><<<dim3(QKVW / 64, Tc / 64, 3), 256, SM64>>>(
            pxh, pxl, qkvh + (size_t)i * Dc * QKVW, qkvl + (size_t)i * Dc * QKVW,
            pqkv, QKVW, Dc, (size_t)Tc * QKVW);
        k_qkprep<<<dim3(Tc, NGc), HDc>>>(pqkv, qnorm + i * HDc, knorm + i * HDc,
                                         cs, sn, khl, kll, vhl, vll);
        if (i == 0) cudaStreamWaitEvent(0, evKV, 0);
        k_flash<<<dim3(Tc / 64, NHc, FZ), 256, SMFL>>>(khl, kll, vhl, vll,
                                                       paop, prsp, is_local);
        k_fcomb<<<NTD / 256, 256>>>(paop, prsp, path, patl);
        if (i == 0) cudaStreamWaitEvent(0, evOut, 0);
        k_mm_t<64, 2><<<dim3(Dc / 64, Tc / 64, 3), 256, SM64>>>(
            path, patl, outh + (size_t)i * Dc * Dc, outl + (size_t)i * Dc * Dc,
            pt1, Dc, Dc, (size_t)Tc * Dc);
        k_fuse<<<Tc, 256>>>(ph, pt1, 3, post_attn + i * Dc, pre_ff + i * Dc,
                            pxh, pxl);
        if (i == 0) cudaStreamWaitEvent(0, evFF, 0);
        k_mmff<<<dim3(FFc / 64, Tc / 64, 2), 256, SMFF>>>(
            pxh, pxl,
            gth + (size_t)i * Dc * FFc, gtl + (size_t)i * Dc * FFc,
            uph + (size_t)i * Dc * FFc, upl + (size_t)i * Dc * FFc,
            pgp, pup2);
        k_gcomb<<<TF / 256, 256>>>(pgp, pup2, pgh, pgl);
        if (i == 0) cudaStreamWaitEvent(0, evDn, 0);
        k_mm_t<64, 2><<<dim3(Dc / 64, Tc / 64, 4), 256, SM64>>>(
            pgh, pgl, dnh + (size_t)i * FFc * Dc, dnl + (size_t)i * FFc * Dc,
            pt1, Dc, FFc, (size_t)Tc * Dc);
        const float* wpre = (i + 1 < Lc) ? pre_attn + (i + 1) * Dc : finalw;
        k_fuse<<<Tc, 256>>>(ph, pt1, 4, post_ff + i * Dc, wpre, pxh, pxl);
    }
    cudaStreamWaitEvent(0, evLM, 0);
    k_mm_t<128, 4><<<dim3(Vocab / 64, Tc / 128, 1), 256, SM128>>>(
        pxh, pxl, lmh, lml, (float*)d_out, Vocab, Dc, 0);
}